// round 8
// baseline (speedup 1.0000x reference)
#include <cuda_runtime.h>
#include <cuda_bf16.h>
#include <math.h>
#include <stdint.h>

// ---------------- problem constants (fixed shapes) ----------------
#define B_   8
#define T_   1024
#define C_   768
#define H_   12
#define HS_  64
#define PH_  32
#define PW_  32
#define NR_  (B_ * T_)          // 8192 rows
#define NC_  ((size_t)NR_ * C_) // 6291456 elems
#define WSZ_ ((size_t)C_ * C_)  // 589824

// ---------------- scratch ----------------
__device__ __align__(16) float g_scratch[10 * NC_ + (size_t)NR_ * 160 + (size_t)NR_ * 64 + (size_t)NR_ * H_];
__device__ __align__(16) __nv_bfloat16 g_acthi[4 * NC_];   // slots: 0=k,1=v,2=r,3=g
__device__ __align__(16) __nv_bfloat16 g_actlo[4 * NC_];
__device__ __align__(16) __nv_bfloat16 g_w5hi[5 * WSZ_];   // W_r,W_k,W_v,W_g,W_o
__device__ __align__(16) __nv_bfloat16 g_w5lo[5 * WSZ_];

#define OFF_XX   ((size_t)0)
#define OFF_XXX  (OFF_XX  + NC_)
#define OFF_T5   (OFF_XXX + NC_)
#define OFF_XW   (OFF_T5  + (size_t)NR_ * 160)
#define OFF_R    (OFF_XW  + NC_)
#define OFF_K    (OFF_R   + NC_)
#define OFF_V    (OFF_K   + NC_)
#define OFF_G    (OFF_V   + NC_)
#define OFF_H1   (OFF_G   + NC_)
#define OFF_WDEC (OFF_H1  + (size_t)NR_ * 64)
#define OFF_Y    (OFF_WDEC+ NC_)
#define OFF_RUK  (OFF_Y   + NC_)

// ========================= helpers ==========================
__device__ __forceinline__ uint32_t smem_u32(const void* p) {
    uint32_t a;
    asm("{ .reg .u64 t; cvta.to.shared.u64 t, %1; cvt.u32.u64 %0, t; }" : "=r"(a) : "l"(p));
    return a;
}
__device__ __forceinline__ void ldsm_x4(uint32_t* r, uint32_t addr) {
    asm volatile("ldmatrix.sync.aligned.m8n8.x4.shared.b16 {%0,%1,%2,%3}, [%4];"
                 : "=r"(r[0]), "=r"(r[1]), "=r"(r[2]), "=r"(r[3]) : "r"(addr));
}
__device__ __forceinline__ void mma_bf16(float* c, const uint32_t* a, uint32_t b0, uint32_t b1) {
    asm volatile("mma.sync.aligned.m16n8k16.row.col.f32.bf16.bf16.f32 "
                 "{%0,%1,%2,%3}, {%4,%5,%6,%7}, {%8,%9}, {%0,%1,%2,%3};"
                 : "+f"(c[0]), "+f"(c[1]), "+f"(c[2]), "+f"(c[3])
                 : "r"(a[0]), "r"(a[1]), "r"(a[2]), "r"(a[3]), "r"(b0), "r"(b1));
}

// ==========================================================================
// bf16-split tensor-core GEMM via mma.sync (R5/R7 proven version)
// ==========================================================================
#define PLANE_   2080
#define ATILE_   (4 * PLANE_)
#define BUFSZ_   (2 * ATILE_)

__global__ void __launch_bounds__(256, 2)
k_gemm_mma(const __nv_bfloat16* __restrict__ Ahi, const __nv_bfloat16* __restrict__ Alo,
           const __nv_bfloat16* __restrict__ Whi, const __nv_bfloat16* __restrict__ Wlo,
           float* __restrict__ Cmat, int doRelu)
{
    __shared__ __align__(16) char sm[2][BUFSZ_];

    const int tid  = threadIdx.x;
    const int warp = tid >> 5;
    const int lane = tid & 31;
    const int m0 = blockIdx.y * 128;
    const int n0 = blockIdx.x * 128;
    const int wm = warp >> 2;
    const int wn = warp & 3;

    float acc[4][4][4];
#pragma unroll
    for (int i = 0; i < 4; i++)
#pragma unroll
        for (int j = 0; j < 4; j++)
#pragma unroll
            for (int q = 0; q < 4; q++) acc[i][j][q] = 0.f;

    const int ldrow = tid >> 1;
    const int ldcb  = (tid & 1) * 2;

    uint4 ra[2], rb[2];

    const uint32_t sb = smem_u32(sm);
    const int lgrp = lane >> 3;
    const int lrl  = lane & 7;

#define LDG_T(c_)                                                               \
    {                                                                           \
        const int seg_ = (c_) / 24;                                             \
        const int kc_  = ((c_) % 24) * 32;                                      \
        const __nv_bfloat16* Ag = (seg_ == 1) ? Alo : Ahi;                      \
        const __nv_bfloat16* Bg = (seg_ == 2) ? Wlo : Whi;                      \
        const __nv_bfloat16* ap = Ag + (size_t)(m0 + ldrow) * C_ + kc_ + ldcb * 8; \
        const __nv_bfloat16* bp = Bg + (size_t)(n0 + ldrow) * C_ + kc_ + ldcb * 8; \
        ra[0] = *(const uint4*)ap; ra[1] = *(const uint4*)(ap + 8);             \
        rb[0] = *(const uint4*)bp; rb[1] = *(const uint4*)(bp + 8);             \
    }

#define STS_T(buf_)                                                             \
    {                                                                           \
        char* b_ = sm[buf_];                                                    \
        *(uint4*)(b_ + (ldcb + 0) * PLANE_ + ldrow * 16) = ra[0];               \
        *(uint4*)(b_ + (ldcb + 1) * PLANE_ + ldrow * 16) = ra[1];               \
        *(uint4*)(b_ + ATILE_ + (ldcb + 0) * PLANE_ + ldrow * 16) = rb[0];      \
        *(uint4*)(b_ + ATILE_ + (ldcb + 1) * PLANE_ + ldrow * 16) = rb[1];      \
    }

    LDG_T(0);
    STS_T(0);
    __syncthreads();

    for (int c = 0; c < 72; c++) {
        const int buf = c & 1;
        const bool hasNext = (c + 1 < 72);
        if (hasNext) LDG_T(c + 1);

        const uint32_t abase = sb + buf * BUFSZ_;
        const uint32_t bbase = abase + ATILE_;

#pragma unroll
        for (int kk = 0; kk < 2; kk++) {
            uint32_t afr[4][4], bfr[2][4];
#pragma unroll
            for (int mt = 0; mt < 4; mt++) {
                int row   = wm * 64 + mt * 16 + (lgrp & 1) * 8 + lrl;
                int chunk = kk * 2 + (lgrp >> 1);
                ldsm_x4(afr[mt], abase + chunk * PLANE_ + row * 16);
            }
#pragma unroll
            for (int nt = 0; nt < 2; nt++) {
                int nr    = wn * 32 + nt * 16 + (lgrp >> 1) * 8 + lrl;
                int chunk = kk * 2 + (lgrp & 1);
                ldsm_x4(bfr[nt], bbase + chunk * PLANE_ + nr * 16);
            }
#pragma unroll
            for (int mt = 0; mt < 4; mt++)
#pragma unroll
                for (int ng = 0; ng < 4; ng++)
                    mma_bf16(acc[mt][ng], afr[mt], bfr[ng >> 1][(ng & 1) * 2 + 0],
                             bfr[ng >> 1][(ng & 1) * 2 + 1]);
        }

        if (hasNext) {
            STS_T(buf ^ 1);
            __syncthreads();
        }
    }
#undef LDG_T
#undef STS_T

#pragma unroll
    for (int mt = 0; mt < 4; mt++) {
        const int r0 = m0 + wm * 64 + mt * 16 + (lane >> 2);
#pragma unroll
        for (int ng = 0; ng < 4; ng++) {
            const int col = n0 + wn * 32 + ng * 8 + (lane & 3) * 2;
            float c0 = acc[mt][ng][0], c1 = acc[mt][ng][1];
            float c2 = acc[mt][ng][2], c3 = acc[mt][ng][3];
            if (doRelu) {
                c0 = fmaxf(c0, 0.f); c1 = fmaxf(c1, 0.f);
                c2 = fmaxf(c2, 0.f); c3 = fmaxf(c3, 0.f);
            }
            *(float2*)(Cmat + (size_t)r0 * C_ + col)       = make_float2(c0, c1);
            *(float2*)(Cmat + (size_t)(r0 + 8) * C_ + col) = make_float2(c2, c3);
        }
    }
}

// ==========================================================================
// Split all five weight matrices into bf16 hi/lo once (float4 vectorized).
// ==========================================================================
__global__ void __launch_bounds__(256)
k_split5(const float* __restrict__ w0, const float* __restrict__ w1,
         const float* __restrict__ w2, const float* __restrict__ w3,
         const float* __restrict__ w4,
         __nv_bfloat16* __restrict__ hi, __nv_bfloat16* __restrict__ lo)
{
    size_t i4 = (size_t)blockIdx.x * blockDim.x + threadIdx.x;   // float4 id < 5*WSZ_/4
    size_t idx = i4 * 4;
    int sel = (int)(idx / WSZ_);
    size_t off = idx % WSZ_;
    const float* src = (sel == 0) ? w0 : (sel == 1) ? w1 : (sel == 2) ? w2 : (sel == 3) ? w3 : w4;
    float4 a = *(const float4*)(src + off);
    __nv_bfloat16 h0 = __float2bfloat16(a.x);
    __nv_bfloat16 h1 = __float2bfloat16(a.y);
    __nv_bfloat16 h2 = __float2bfloat16(a.z);
    __nv_bfloat16 h3 = __float2bfloat16(a.w);
    __nv_bfloat162 hp0, hp1, lp0, lp1;
    hp0.x = h0; hp0.y = h1; hp1.x = h2; hp1.y = h3;
    lp0.x = __float2bfloat16(a.x - __bfloat162float(h0));
    lp0.y = __float2bfloat16(a.y - __bfloat162float(h1));
    lp1.x = __float2bfloat16(a.z - __bfloat162float(h2));
    lp1.y = __float2bfloat16(a.w - __bfloat162float(h3));
    *(uint2*)(hi + idx) = make_uint2(*(uint32_t*)&hp0, *(uint32_t*)&hp1);
    *(uint2*)(lo + idx) = make_uint2(*(uint32_t*)&lp0, *(uint32_t*)&lp1);
}

// ==========================================================================
// Kernel 1: q-shift (float4) -> xx = shift(x) - x ; xxx = x + xx * maa_x
// Quarter index is constant within an aligned 4-col group (16-col blocks).
// ==========================================================================
__global__ void __launch_bounds__(256)
k_shift(const float* __restrict__ x, const float* __restrict__ maa_x,
        float* __restrict__ xx, float* __restrict__ xxx)
{
    size_t i4 = (size_t)blockIdx.x * blockDim.x + threadIdx.x;   // < NC_/4
    size_t idx = i4 * 4;
    int c  = (int)(idx % C_);
    int bt = (int)(idx / C_);
    int t  = bt % T_;
    int w  = t % PW_;
    int h  = t / PW_;
    int quarter = (c & (HS_ - 1)) >> 4;

    float4 src = make_float4(0.f, 0.f, 0.f, 0.f);
    if (quarter == 0)      { if (w > 0)       src = *(const float4*)(x + idx - C_); }
    else if (quarter == 1) { if (w < PW_ - 1) src = *(const float4*)(x + idx + C_); }
    else if (quarter == 2) { if (h > 0)       src = *(const float4*)(x + idx - PW_ * C_); }
    else                   { if (h < PH_ - 1) src = *(const float4*)(x + idx + PW_ * C_); }

    float4 xv = *(const float4*)(x + idx);
    float4 mv = *(const float4*)(maa_x + c);
    float4 d, o;
    d.x = src.x - xv.x; d.y = src.y - xv.y; d.z = src.z - xv.z; d.w = src.w - xv.w;
    o.x = fmaf(d.x, mv.x, xv.x); o.y = fmaf(d.y, mv.y, xv.y);
    o.z = fmaf(d.z, mv.z, xv.z); o.w = fmaf(d.w, mv.w, xv.w);
    *(float4*)(xx + idx)  = d;
    *(float4*)(xxx + idx) = o;
}

// ==========================================================================
// Pipelined tiled fp32 GEMM (small N/K GEMMs only)
// ==========================================================================
template<int EPI, bool BNT>
__global__ void __launch_bounds__(256, 2)
k_gemm(const float* __restrict__ A, const float* __restrict__ B,
       float* __restrict__ Cmat, int M, int N, int K, const float* __restrict__ bias)
{
    __shared__ float As[2][16][132];
    __shared__ float Bs[2][16][132];

    const int m0   = blockIdx.y * 128;
    const int n0   = blockIdx.x * 128;
    const int tid  = threadIdx.x;
    const int warp = tid >> 5;
    const int lane = tid & 31;
    const int tm   = (warp >> 2) * 64 + (lane >> 2) * 8;
    const int tn   = (warp & 3) * 32 + (lane & 3) * 8;

    float acc[8][8];
#pragma unroll
    for (int i = 0; i < 8; i++)
#pragma unroll
        for (int j = 0; j < 8; j++) acc[i][j] = 0.f;

    float4 aR[2], bR[2];

#define LDG_TILE(k0_)                                                          \
    {                                                                          \
        _Pragma("unroll")                                                      \
        for (int l = 0; l < 2; l++) {                                          \
            int e  = tid + l * 256;                                            \
            int am = e >> 2;                                                   \
            int ak = (e & 3) * 4;                                              \
            aR[l] = *(const float4*)(A + (size_t)(m0 + am) * K + (k0_) + ak);  \
            if (BNT) {                                                         \
                int bn = e >> 2;                                               \
                int bk = (e & 3) * 4;                                          \
                bR[l] = make_float4(0.f, 0.f, 0.f, 0.f);                       \
                if (n0 + bn < N)                                               \
                    bR[l] = *(const float4*)(B + (size_t)(n0 + bn) * K + (k0_) + bk); \
            } else {                                                           \
                int bk = e >> 5;                                               \
                int bn = (e & 31) * 4;                                         \
                bR[l] = make_float4(0.f, 0.f, 0.f, 0.f);                       \
                if (n0 + bn < N)                                               \
                    bR[l] = *(const float4*)(B + (size_t)((k0_) + bk) * N + n0 + bn); \
            }                                                                  \
        }                                                                      \
    }

#define STS_TILE(buf_)                                                         \
    {                                                                          \
        _Pragma("unroll")                                                      \
        for (int l = 0; l < 2; l++) {                                          \
            int e  = tid + l * 256;                                            \
            int am = e >> 2;                                                   \
            int ak = (e & 3) * 4;                                              \
            As[buf_][ak + 0][am] = aR[l].x; As[buf_][ak + 1][am] = aR[l].y;    \
            As[buf_][ak + 2][am] = aR[l].z; As[buf_][ak + 3][am] = aR[l].w;    \
            if (BNT) {                                                         \
                int bn = e >> 2;                                               \
                int bk = (e & 3) * 4;                                          \
                Bs[buf_][bk + 0][bn] = bR[l].x; Bs[buf_][bk + 1][bn] = bR[l].y;\
                Bs[buf_][bk + 2][bn] = bR[l].z; Bs[buf_][bk + 3][bn] = bR[l].w;\
            } else {                                                           \
                int bk = e >> 5;                                               \
                int bn = (e & 31) * 4;                                         \
                *(float4*)(&Bs[buf_][bk][bn]) = bR[l];                         \
            }                                                                  \
        }                                                                      \
    }

    LDG_TILE(0);
    STS_TILE(0);
    __syncthreads();

    int buf = 0;
    for (int k0 = 0; k0 < K; k0 += 16) {
        const bool hasNext = (k0 + 16 < K);
        if (hasNext) LDG_TILE(k0 + 16);

#pragma unroll
        for (int kk = 0; kk < 16; kk++) {
            float a[8], b[8];
            *(float4*)(a)     = *(const float4*)(&As[buf][kk][tm]);
            *(float4*)(a + 4) = *(const float4*)(&As[buf][kk][tm + 4]);
            *(float4*)(b)     = *(const float4*)(&Bs[buf][kk][tn]);
            *(float4*)(b + 4) = *(const float4*)(&Bs[buf][kk][tn + 4]);
#pragma unroll
            for (int i = 0; i < 8; i++)
#pragma unroll
                for (int j = 0; j < 8; j++)
                    acc[i][j] = fmaf(a[i], b[j], acc[i][j]);
        }

        if (hasNext) {
            STS_TILE(buf ^ 1);
            __syncthreads();
            buf ^= 1;
        }
    }
#undef LDG_TILE
#undef STS_TILE

#pragma unroll
    for (int i = 0; i < 8; i++) {
        int m = m0 + tm + i;
#pragma unroll
        for (int j = 0; j < 8; j++) {
            int n = n0 + tn + j;
            if (n < N) {
                float v = acc[i][j];
                if (EPI == 1) v = tanhf(v);
                else if (EPI == 2) v = fmaxf(v, 0.f);
                else if (EPI == 3) v = expf(-expf(bias[n] + v));
                Cmat[(size_t)m * N + n] = v;
            }
        }
    }
}

// ==========================================================================
// Fused token-mix: 16-row tiles, 8 outputs/thread.
// f=0 -> xw (fp32); f=1..4 -> bf16 hi/lo (slots 0=k,1=v,2=r,3=g)
// ==========================================================================
__global__ void __launch_bounds__(256, 2)
k_mix(const float* __restrict__ x, const float* __restrict__ xx,
      const float* __restrict__ t5, const float* __restrict__ w2,
      const float* __restrict__ ma0, const float* __restrict__ ma1,
      const float* __restrict__ ma2, const float* __restrict__ ma3,
      const float* __restrict__ ma4,
      float* __restrict__ xw,
      __nv_bfloat16* __restrict__ acthi, __nv_bfloat16* __restrict__ actlo)
{
    const int r0  = blockIdx.x * 16;
    const int c0  = blockIdx.y * 128;
    const int tid = threadIdx.x;
    const int cl  = tid & 127;
    const int rh  = tid >> 7;

    __shared__ __align__(16) float tsh[16][36];
    __shared__ float wsh[32][128];

    float xr_[8], xxr_[8];
#pragma unroll
    for (int kk = 0; kk < 8; kk++) {
        size_t idx = (size_t)(r0 + rh + 2 * kk) * C_ + c0 + cl;
        xr_[kk]  = x[idx];
        xxr_[kk] = xx[idx];
    }

    // preload the 5 maa values (avoids indexed pointer array)
    float mfv[5];
    mfv[0] = ma0[c0 + cl]; mfv[1] = ma1[c0 + cl]; mfv[2] = ma2[c0 + cl];
    mfv[3] = ma3[c0 + cl]; mfv[4] = ma4[c0 + cl];

    for (int f = 0; f < 5; f++) {   // not unrolled (sync inside)
        {
            int e = tid;            // 512 elements: 2 per thread
            tsh[e >> 5][e & 31] = t5[(size_t)(r0 + (e >> 5)) * 160 + f * 32 + (e & 31)];
            e = tid + 256;
            tsh[e >> 5][e & 31] = t5[(size_t)(r0 + (e >> 5)) * 160 + f * 32 + (e & 31)];
        }
#pragma unroll
        for (int l = 0; l < 16; l++) {
            int e = tid + l * 256;
            wsh[e >> 7][e & 127] = w2[(size_t)(f * 32 + (e >> 7)) * C_ + c0 + (e & 127)];
        }
        __syncthreads();

        float wreg[32];
#pragma unroll
        for (int rr = 0; rr < 32; rr++) wreg[rr] = wsh[rr][cl];

        const float mf = mfv[f];
        const size_t slotoff = (size_t)(f - 1) * NC_;
#pragma unroll
        for (int kk = 0; kk < 8; kk++) {
            const int row = rh + 2 * kk;
            const float4* trow = (const float4*)(&tsh[row][0]);
            float a = 0.f;
#pragma unroll
            for (int q = 0; q < 8; q++) {
                float4 t4 = trow[q];
                a = fmaf(t4.x, wreg[4 * q + 0], a);
                a = fmaf(t4.y, wreg[4 * q + 1], a);
                a = fmaf(t4.z, wreg[4 * q + 2], a);
                a = fmaf(t4.w, wreg[4 * q + 3], a);
            }
            size_t idx = (size_t)(r0 + row) * C_ + c0 + cl;
            float val = fmaf(xxr_[kk], mf + a, xr_[kk]);
            if (f == 0) {
                xw[idx] = val;
            } else {
                __nv_bfloat16 h = __float2bfloat16(val);
                acthi[slotoff + idx] = h;
                actlo[slotoff + idx] = __float2bfloat16(val - __bfloat162float(h));
            }
        }
        __syncthreads();
    }
}

// ==========================================================================
// ruk[row,h] = sum_j r*u*k
// ==========================================================================
__global__ void k_ruk(const float* __restrict__ r, const float* __restrict__ k,
                      const float* __restrict__ u, float* __restrict__ ruk)
{
    const int row = blockIdx.x;
    const int c   = threadIdx.x;
    const int h   = c >> 6;
    const int j   = c & 63;
    size_t idx = (size_t)row * C_ + c;
    float p = r[idx] * u[c] * k[idx];
#pragma unroll
    for (int off = 16; off; off >>= 1) p += __shfl_xor_sync(0xffffffffu, p, off);
    __shared__ float ws[24];
    if ((c & 31) == 0) ws[c >> 5] = p;
    __syncthreads();
    if (j == 0) ruk[(size_t)row * H_ + h] = ws[2 * h] + ws[2 * h + 1];
}

// ==========================================================================
// WKV6 recurrence (256 threads, j split in quarters)
// ==========================================================================
__global__ void __launch_bounds__(256)
k_wkv(const float* __restrict__ r, const float* __restrict__ k,
      const float* __restrict__ v, const float* __restrict__ wd,
      const float* __restrict__ ruk, float* __restrict__ y)
{
    const int bh = blockIdx.x;
    const int b  = bh / H_;
    const int h  = bh % H_;
    const int tid = threadIdx.x;
    const int i  = tid & 63;
    const int q  = tid >> 6;

    __shared__ __align__(16) float sr[64];
    __shared__ __align__(16) float sk[64];
    __shared__ __align__(16) float sw[64];
    __shared__ __align__(16) float sv[64];
    __shared__ float part[3][64];

    float S[16];
#pragma unroll
    for (int jj = 0; jj < 16; jj++) S[jj] = 0.f;

    const size_t base  = (size_t)b * T_ * C_ + h * 64;
    const size_t rbase = (size_t)b * T_ * H_ + h;

    const float* mysrc = (q == 0) ? r : (q == 1) ? k : (q == 2) ? wd : v;
    float cur = mysrc[base + i];

    for (int t = 0; t < T_; t++) {
        if (q == 0)      sr[i] = cur;
        else if (q == 1) sk[i] = cur;
        else if (q == 2) sw[i] = cur;
        else             sv[i] = cur;
        __syncthreads();

        float nxt = cur;
        if (t + 1 < T_) nxt = mysrc[base + (size_t)(t + 1) * C_ + i];

        const float vi = sv[i];
        float yp = 0.f;
#pragma unroll
        for (int g4 = 0; g4 < 4; g4++) {
            float4 r4 = *(const float4*)(sr + q * 16 + g4 * 4);
            float4 k4 = *(const float4*)(sk + q * 16 + g4 * 4);
            float4 w4 = *(const float4*)(sw + q * 16 + g4 * 4);
            float kv;
            kv = k4.x * vi; yp = fmaf(r4.x, S[4*g4+0], yp); S[4*g4+0] = fmaf(w4.x, S[4*g4+0], kv);
            kv = k4.y * vi; yp = fmaf(r4.y, S[4*g4+1], yp); S[4*g4+1] = fmaf(w4.y, S[4*g4+1], kv);
            kv = k4.z * vi; yp = fmaf(r4.z, S[4*g4+2], yp); S[4*g4+2] = fmaf(w4.z, S[4*g4+2], kv);
            kv = k4.w * vi; yp = fmaf(r4.w, S[4*g4+3], yp); S[4*g4+3] = fmaf(w4.w, S[4*g4+3], kv);
        }
        if (q) part[q - 1][i] = yp;
        __syncthreads();

        if (q == 0) {
            float yv = yp + part[0][i] + part[1][i] + part[2][i];
            yv = fmaf(ruk[rbase + (size_t)t * H_], vi, yv);
            y[base + (size_t)t * C_ + i] = yv;
        }
        cur = nxt;
    }
}

// ==========================================================================
// GroupNorm * g -> bf16 hi/lo split directly (for the W_o GEMM)
// ==========================================================================
__global__ void k_gnorm(const float* __restrict__ y, const float* __restrict__ gbuf,
                        const float* __restrict__ lnw, const float* __restrict__ lnb,
                        __nv_bfloat16* __restrict__ hi, __nv_bfloat16* __restrict__ lo)
{
    const int row = blockIdx.x;
    const int c   = threadIdx.x;
    size_t idx = (size_t)row * C_ + c;
    float v = y[idx];
    float s = v, s2 = v * v;
#pragma unroll
    for (int off = 16; off; off >>= 1) {
        s  += __shfl_xor_sync(0xffffffffu, s,  off);
        s2 += __shfl_xor_sync(0xffffffffu, s2, off);
    }
    __shared__ float as[24], as2[24];
    if ((c & 31) == 0) { as[c >> 5] = s; as2[c >> 5] = s2; }
    __syncthreads();
    const int g = c >> 6;
    float sum  = as[2 * g]  + as[2 * g + 1];
    float sum2 = as2[2 * g] + as2[2 * g + 1];
    float mu   = sum * (1.f / 64.f);
    float var  = sum2 * (1.f / 64.f) - mu * mu;
    float nv   = (v - mu) * rsqrtf(var + 1e-5f);
    float val  = fmaf(nv, lnw[c], lnb[c]) * gbuf[idx];
    __nv_bfloat16 h = __float2bfloat16(val);
    hi[idx] = h;
    lo[idx] = __float2bfloat16(val - __bfloat162float(h));
}

// ==========================================================================
// Host launcher
// ==========================================================================
extern "C" void kernel_launch(void* const* d_in, const int* in_sizes, int n_in,
                              void* d_out, int out_size)
{
    const float* x     = (const float*)d_in[0];
    const float* W_r   = (const float*)d_in[1];
    const float* W_k   = (const float*)d_in[2];
    const float* W_v   = (const float*)d_in[3];
    const float* W_g   = (const float*)d_in[4];
    const float* W_o   = (const float*)d_in[5];
    const float* maa_x = (const float*)d_in[6];
    const float* maa_w = (const float*)d_in[7];
    const float* maa_k = (const float*)d_in[8];
    const float* maa_v = (const float*)d_in[9];
    const float* maa_r = (const float*)d_in[10];
    const float* maa_g = (const float*)d_in[11];
    const float* maa_w1= (const float*)d_in[12];
    const float* maa_w2= (const float*)d_in[13];
    const float* tdec  = (const float*)d_in[14];
    const float* dec_w1= (const float*)d_in[15];
    const float* dec_w2= (const float*)d_in[16];
    const float* faaaa = (const float*)d_in[17];
    const float* ln_w  = (const float*)d_in[18];
    const float* ln_b  = (const float*)d_in[19];
    (void)in_sizes; (void)n_in; (void)out_size;

    float* S = nullptr;
    cudaGetSymbolAddress((void**)&S, g_scratch);
    __nv_bfloat16 *acthi = nullptr, *actlo = nullptr, *w5hi = nullptr, *w5lo = nullptr;
    cudaGetSymbolAddress((void**)&acthi, g_acthi);
    cudaGetSymbolAddress((void**)&actlo, g_actlo);
    cudaGetSymbolAddress((void**)&w5hi, g_w5hi);
    cudaGetSymbolAddress((void**)&w5lo, g_w5lo);

    float* xx   = S + OFF_XX;
    float* xxx  = S + OFF_XXX;
    float* t5   = S + OFF_T5;
    float* xw   = S + OFF_XW;
    float* rb   = S + OFF_R;
    float* kb   = S + OFF_K;
    float* vb   = S + OFF_V;
    float* gb   = S + OFF_G;
    float* h1   = S + OFF_H1;
    float* wdec = S + OFF_WDEC;
    float* yb   = S + OFF_Y;
    float* ruk  = S + OFF_RUK;
    float* outp = (float*)d_out;

    const dim3 gTC(C_ / 128, NR_ / 128);   // (6, 64)

    // 0. split all 5 weights
    k_split5<<<(unsigned)(5 * WSZ_ / 4 / 256), 256>>>(W_r, W_k, W_v, W_g, W_o, w5hi, w5lo);

    // 1. shift + xxx (float4)
    k_shift<<<(unsigned)(NC_ / 4 / 256), 256>>>(x, maa_x, xx, xxx);

    // 2. t5 = tanh(xxx @ maa_w1)
    k_gemm<1, false><<<dim3(2, NR_ / 128), 256>>>(xxx, maa_w1, t5, NR_, 160, C_, nullptr);

    // 3. fused token mix -> xw fp32 + bf16 hi/lo for k,v,r,g
    k_mix<<<dim3(NR_ / 16, C_ / 128), 256>>>(x, xx, t5, maa_w2,
                                             maa_w, maa_k, maa_v, maa_r, maa_g,
                                             xw, acthi, actlo);

    // 4. big NT GEMMs (bf16-split mma.sync). act slots: 0=k,1=v,2=r,3=g
    k_gemm_mma<<<gTC, 256>>>(acthi + 2 * NC_, actlo + 2 * NC_,
                             w5hi + 0 * WSZ_, w5lo + 0 * WSZ_, rb, 0);
    k_gemm_mma<<<gTC, 256>>>(acthi + 0 * NC_, actlo + 0 * NC_,
                             w5hi + 1 * WSZ_, w5lo + 1 * WSZ_, kb, 0);
    k_gemm_mma<<<gTC, 256>>>(acthi + 1 * NC_, actlo + 1 * NC_,
                             w5hi + 2 * WSZ_, w5lo + 2 * WSZ_, vb, 0);
    k_gemm_mma<<<gTC, 256>>>(acthi + 3 * NC_, actlo + 3 * NC_,
                             w5hi + 3 * WSZ_, w5lo + 3 * WSZ_, gb, 1);  // relu

    // 5. decay path (small fp32 GEMMs)
    k_gemm<1, false><<<dim3(1, NR_ / 128), 256>>>(xw, dec_w1, h1, NR_, 64, C_, nullptr);
    k_gemm<3, false><<<dim3(C_ / 128, NR_ / 128), 256>>>(h1, dec_w2, wdec, NR_, C_, 64, tdec);

    // 6. wkv recurrence
    k_ruk<<<NR_, C_>>>(rb, kb, faaaa, ruk);
    k_wkv<<<B_ * H_, 256>>>(rb, kb, vb, wdec, ruk, yb);

    // 7. groupnorm * g -> bf16 pair (reuse act slot 0)
    k_gnorm<<<NR_, C_>>>(yb, gb, ln_w, ln_b, acthi, actlo);

    // 8. out = yn @ W_o^T
    k_gemm_mma<<<gTC, 256>>>(acthi, actlo,
                             w5hi + 4 * WSZ_, w5lo + 4 * WSZ_, outp, 0);
}

// round 9
// speedup vs baseline: 1.0365x; 1.0365x over previous
#include <cuda_runtime.h>
#include <cuda_bf16.h>
#include <math.h>
#include <stdint.h>

// ---------------- problem constants (fixed shapes) ----------------
#define B_   8
#define T_   1024
#define C_   768
#define H_   12
#define HS_  64
#define PH_  32
#define PW_  32
#define NR_  (B_ * T_)          // 8192 rows
#define NC_  ((size_t)NR_ * C_) // 6291456 elems
#define WSZ_ ((size_t)C_ * C_)  // 589824

// ---------------- scratch ----------------
__device__ __align__(16) float g_scratch[10 * NC_ + (size_t)NR_ * 160 + (size_t)NR_ * 64 + (size_t)NR_ * H_];
__device__ __align__(16) __nv_bfloat16 g_acthi[4 * NC_];   // slots: 0=k,1=v,2=r,3=g
__device__ __align__(16) __nv_bfloat16 g_actlo[4 * NC_];
__device__ __align__(16) __nv_bfloat16 g_w5hi[5 * WSZ_];   // W_r,W_k,W_v,W_g,W_o
__device__ __align__(16) __nv_bfloat16 g_w5lo[5 * WSZ_];

#define OFF_XX   ((size_t)0)
#define OFF_XXX  (OFF_XX  + NC_)
#define OFF_T5   (OFF_XXX + NC_)
#define OFF_XW   (OFF_T5  + (size_t)NR_ * 160)
#define OFF_R    (OFF_XW  + NC_)
#define OFF_K    (OFF_R   + NC_)
#define OFF_V    (OFF_K   + NC_)
#define OFF_G    (OFF_V   + NC_)
#define OFF_H1   (OFF_G   + NC_)
#define OFF_WDEC (OFF_H1  + (size_t)NR_ * 64)
#define OFF_Y    (OFF_WDEC+ NC_)
#define OFF_RUK  (OFF_Y   + NC_)

// ========================= helpers ==========================
__device__ __forceinline__ uint32_t smem_u32(const void* p) {
    uint32_t a;
    asm("{ .reg .u64 t; cvta.to.shared.u64 t, %1; cvt.u32.u64 %0, t; }" : "=r"(a) : "l"(p));
    return a;
}
__device__ __forceinline__ void ldsm_x4(uint32_t* r, uint32_t addr) {
    asm volatile("ldmatrix.sync.aligned.m8n8.x4.shared.b16 {%0,%1,%2,%3}, [%4];"
                 : "=r"(r[0]), "=r"(r[1]), "=r"(r[2]), "=r"(r[3]) : "r"(addr));
}
__device__ __forceinline__ void mma_bf16(float* c, const uint32_t* a, uint32_t b0, uint32_t b1) {
    asm volatile("mma.sync.aligned.m16n8k16.row.col.f32.bf16.bf16.f32 "
                 "{%0,%1,%2,%3}, {%4,%5,%6,%7}, {%8,%9}, {%0,%1,%2,%3};"
                 : "+f"(c[0]), "+f"(c[1]), "+f"(c[2]), "+f"(c[3])
                 : "r"(a[0]), "r"(a[1]), "r"(a[2]), "r"(a[3]), "r"(b0), "r"(b1));
}

// ==========================================================================
// bf16-split tensor-core GEMM via mma.sync (R5/R7 proven version)
// ==========================================================================
#define PLANE_   2080
#define ATILE_   (4 * PLANE_)
#define BUFSZ_   (2 * ATILE_)

__global__ void __launch_bounds__(256, 2)
k_gemm_mma(const __nv_bfloat16* __restrict__ Ahi, const __nv_bfloat16* __restrict__ Alo,
           const __nv_bfloat16* __restrict__ Whi, const __nv_bfloat16* __restrict__ Wlo,
           float* __restrict__ Cmat, int doRelu)
{
    __shared__ __align__(16) char sm[2][BUFSZ_];

    const int tid  = threadIdx.x;
    const int warp = tid >> 5;
    const int lane = tid & 31;
    const int m0 = blockIdx.y * 128;
    const int n0 = blockIdx.x * 128;
    const int wm = warp >> 2;
    const int wn = warp & 3;

    float acc[4][4][4];
#pragma unroll
    for (int i = 0; i < 4; i++)
#pragma unroll
        for (int j = 0; j < 4; j++)
#pragma unroll
            for (int q = 0; q < 4; q++) acc[i][j][q] = 0.f;

    const int ldrow = tid >> 1;
    const int ldcb  = (tid & 1) * 2;

    uint4 ra[2], rb[2];

    const uint32_t sb = smem_u32(sm);
    const int lgrp = lane >> 3;
    const int lrl  = lane & 7;

#define LDG_T(c_)                                                               \
    {                                                                           \
        const int seg_ = (c_) / 24;                                             \
        const int kc_  = ((c_) % 24) * 32;                                      \
        const __nv_bfloat16* Ag = (seg_ == 1) ? Alo : Ahi;                      \
        const __nv_bfloat16* Bg = (seg_ == 2) ? Wlo : Whi;                      \
        const __nv_bfloat16* ap = Ag + (size_t)(m0 + ldrow) * C_ + kc_ + ldcb * 8; \
        const __nv_bfloat16* bp = Bg + (size_t)(n0 + ldrow) * C_ + kc_ + ldcb * 8; \
        ra[0] = *(const uint4*)ap; ra[1] = *(const uint4*)(ap + 8);             \
        rb[0] = *(const uint4*)bp; rb[1] = *(const uint4*)(bp + 8);             \
    }

#define STS_T(buf_)                                                             \
    {                                                                           \
        char* b_ = sm[buf_];                                                    \
        *(uint4*)(b_ + (ldcb + 0) * PLANE_ + ldrow * 16) = ra[0];               \
        *(uint4*)(b_ + (ldcb + 1) * PLANE_ + ldrow * 16) = ra[1];               \
        *(uint4*)(b_ + ATILE_ + (ldcb + 0) * PLANE_ + ldrow * 16) = rb[0];      \
        *(uint4*)(b_ + ATILE_ + (ldcb + 1) * PLANE_ + ldrow * 16) = rb[1];      \
    }

    LDG_T(0);
    STS_T(0);
    __syncthreads();

    for (int c = 0; c < 72; c++) {
        const int buf = c & 1;
        const bool hasNext = (c + 1 < 72);
        if (hasNext) LDG_T(c + 1);

        const uint32_t abase = sb + buf * BUFSZ_;
        const uint32_t bbase = abase + ATILE_;

#pragma unroll
        for (int kk = 0; kk < 2; kk++) {
            uint32_t afr[4][4], bfr[2][4];
#pragma unroll
            for (int mt = 0; mt < 4; mt++) {
                int row   = wm * 64 + mt * 16 + (lgrp & 1) * 8 + lrl;
                int chunk = kk * 2 + (lgrp >> 1);
                ldsm_x4(afr[mt], abase + chunk * PLANE_ + row * 16);
            }
#pragma unroll
            for (int nt = 0; nt < 2; nt++) {
                int nr    = wn * 32 + nt * 16 + (lgrp >> 1) * 8 + lrl;
                int chunk = kk * 2 + (lgrp & 1);
                ldsm_x4(bfr[nt], bbase + chunk * PLANE_ + nr * 16);
            }
#pragma unroll
            for (int mt = 0; mt < 4; mt++)
#pragma unroll
                for (int ng = 0; ng < 4; ng++)
                    mma_bf16(acc[mt][ng], afr[mt], bfr[ng >> 1][(ng & 1) * 2 + 0],
                             bfr[ng >> 1][(ng & 1) * 2 + 1]);
        }

        if (hasNext) {
            STS_T(buf ^ 1);
            __syncthreads();
        }
    }
#undef LDG_T
#undef STS_T

#pragma unroll
    for (int mt = 0; mt < 4; mt++) {
        const int r0 = m0 + wm * 64 + mt * 16 + (lane >> 2);
#pragma unroll
        for (int ng = 0; ng < 4; ng++) {
            const int col = n0 + wn * 32 + ng * 8 + (lane & 3) * 2;
            float c0 = acc[mt][ng][0], c1 = acc[mt][ng][1];
            float c2 = acc[mt][ng][2], c3 = acc[mt][ng][3];
            if (doRelu) {
                c0 = fmaxf(c0, 0.f); c1 = fmaxf(c1, 0.f);
                c2 = fmaxf(c2, 0.f); c3 = fmaxf(c3, 0.f);
            }
            *(float2*)(Cmat + (size_t)r0 * C_ + col)       = make_float2(c0, c1);
            *(float2*)(Cmat + (size_t)(r0 + 8) * C_ + col) = make_float2(c2, c3);
        }
    }
}

// ==========================================================================
// Split all five weight matrices into bf16 hi/lo once (float4 vectorized).
// ==========================================================================
__global__ void __launch_bounds__(256)
k_split5(const float* __restrict__ w0, const float* __restrict__ w1,
         const float* __restrict__ w2, const float* __restrict__ w3,
         const float* __restrict__ w4,
         __nv_bfloat16* __restrict__ hi, __nv_bfloat16* __restrict__ lo)
{
    size_t i4 = (size_t)blockIdx.x * blockDim.x + threadIdx.x;
    size_t idx = i4 * 4;
    int sel = (int)(idx / WSZ_);
    size_t off = idx % WSZ_;
    const float* src = (sel == 0) ? w0 : (sel == 1) ? w1 : (sel == 2) ? w2 : (sel == 3) ? w3 : w4;
    float4 a = *(const float4*)(src + off);
    __nv_bfloat16 h0 = __float2bfloat16(a.x);
    __nv_bfloat16 h1 = __float2bfloat16(a.y);
    __nv_bfloat16 h2 = __float2bfloat16(a.z);
    __nv_bfloat16 h3 = __float2bfloat16(a.w);
    __nv_bfloat162 hp0, hp1, lp0, lp1;
    hp0.x = h0; hp0.y = h1; hp1.x = h2; hp1.y = h3;
    lp0.x = __float2bfloat16(a.x - __bfloat162float(h0));
    lp0.y = __float2bfloat16(a.y - __bfloat162float(h1));
    lp1.x = __float2bfloat16(a.z - __bfloat162float(h2));
    lp1.y = __float2bfloat16(a.w - __bfloat162float(h3));
    *(uint2*)(hi + idx) = make_uint2(*(uint32_t*)&hp0, *(uint32_t*)&hp1);
    *(uint2*)(lo + idx) = make_uint2(*(uint32_t*)&lp0, *(uint32_t*)&lp1);
}

// ==========================================================================
// Kernel 1: q-shift (float4) -> xx = shift(x) - x ; xxx = x + xx * maa_x
// ==========================================================================
__global__ void __launch_bounds__(256)
k_shift(const float* __restrict__ x, const float* __restrict__ maa_x,
        float* __restrict__ xx, float* __restrict__ xxx)
{
    size_t i4 = (size_t)blockIdx.x * blockDim.x + threadIdx.x;
    size_t idx = i4 * 4;
    int c  = (int)(idx % C_);
    int bt = (int)(idx / C_);
    int t  = bt % T_;
    int w  = t % PW_;
    int h  = t / PW_;
    int quarter = (c & (HS_ - 1)) >> 4;

    float4 src = make_float4(0.f, 0.f, 0.f, 0.f);
    if (quarter == 0)      { if (w > 0)       src = *(const float4*)(x + idx - C_); }
    else if (quarter == 1) { if (w < PW_ - 1) src = *(const float4*)(x + idx + C_); }
    else if (quarter == 2) { if (h > 0)       src = *(const float4*)(x + idx - PW_ * C_); }
    else                   { if (h < PH_ - 1) src = *(const float4*)(x + idx + PW_ * C_); }

    float4 xv = *(const float4*)(x + idx);
    float4 mv = *(const float4*)(maa_x + c);
    float4 d, o;
    d.x = src.x - xv.x; d.y = src.y - xv.y; d.z = src.z - xv.z; d.w = src.w - xv.w;
    o.x = fmaf(d.x, mv.x, xv.x); o.y = fmaf(d.y, mv.y, xv.y);
    o.z = fmaf(d.z, mv.z, xv.z); o.w = fmaf(d.w, mv.w, xv.w);
    *(float4*)(xx + idx)  = d;
    *(float4*)(xxx + idx) = o;
}

// ==========================================================================
// Pipelined tiled fp32 GEMM (small N/K GEMMs only)
// ==========================================================================
template<int EPI, bool BNT>
__global__ void __launch_bounds__(256, 2)
k_gemm(const float* __restrict__ A, const float* __restrict__ B,
       float* __restrict__ Cmat, int M, int N, int K, const float* __restrict__ bias)
{
    __shared__ float As[2][16][132];
    __shared__ float Bs[2][16][132];

    const int m0   = blockIdx.y * 128;
    const int n0   = blockIdx.x * 128;
    const int tid  = threadIdx.x;
    const int warp = tid >> 5;
    const int lane = tid & 31;
    const int tm   = (warp >> 2) * 64 + (lane >> 2) * 8;
    const int tn   = (warp & 3) * 32 + (lane & 3) * 8;

    float acc[8][8];
#pragma unroll
    for (int i = 0; i < 8; i++)
#pragma unroll
        for (int j = 0; j < 8; j++) acc[i][j] = 0.f;

    float4 aR[2], bR[2];

#define LDG_TILE(k0_)                                                          \
    {                                                                          \
        _Pragma("unroll")                                                      \
        for (int l = 0; l < 2; l++) {                                          \
            int e  = tid + l * 256;                                            \
            int am = e >> 2;                                                   \
            int ak = (e & 3) * 4;                                              \
            aR[l] = *(const float4*)(A + (size_t)(m0 + am) * K + (k0_) + ak);  \
            if (BNT) {                                                         \
                int bn = e >> 2;                                               \
                int bk = (e & 3) * 4;                                          \
                bR[l] = make_float4(0.f, 0.f, 0.f, 0.f);                       \
                if (n0 + bn < N)                                               \
                    bR[l] = *(const float4*)(B + (size_t)(n0 + bn) * K + (k0_) + bk); \
            } else {                                                           \
                int bk = e >> 5;                                               \
                int bn = (e & 31) * 4;                                         \
                bR[l] = make_float4(0.f, 0.f, 0.f, 0.f);                       \
                if (n0 + bn < N)                                               \
                    bR[l] = *(const float4*)(B + (size_t)((k0_) + bk) * N + n0 + bn); \
            }                                                                  \
        }                                                                      \
    }

#define STS_TILE(buf_)                                                         \
    {                                                                          \
        _Pragma("unroll")                                                      \
        for (int l = 0; l < 2; l++) {                                          \
            int e  = tid + l * 256;                                            \
            int am = e >> 2;                                                   \
            int ak = (e & 3) * 4;                                              \
            As[buf_][ak + 0][am] = aR[l].x; As[buf_][ak + 1][am] = aR[l].y;    \
            As[buf_][ak + 2][am] = aR[l].z; As[buf_][ak + 3][am] = aR[l].w;    \
            if (BNT) {                                                         \
                int bn = e >> 2;                                               \
                int bk = (e & 3) * 4;                                          \
                Bs[buf_][bk + 0][bn] = bR[l].x; Bs[buf_][bk + 1][bn] = bR[l].y;\
                Bs[buf_][bk + 2][bn] = bR[l].z; Bs[buf_][bk + 3][bn] = bR[l].w;\
            } else {                                                           \
                int bk = e >> 5;                                               \
                int bn = (e & 31) * 4;                                         \
                *(float4*)(&Bs[buf_][bk][bn]) = bR[l];                         \
            }                                                                  \
        }                                                                      \
    }

    LDG_TILE(0);
    STS_TILE(0);
    __syncthreads();

    int buf = 0;
    for (int k0 = 0; k0 < K; k0 += 16) {
        const bool hasNext = (k0 + 16 < K);
        if (hasNext) LDG_TILE(k0 + 16);

#pragma unroll
        for (int kk = 0; kk < 16; kk++) {
            float a[8], b[8];
            *(float4*)(a)     = *(const float4*)(&As[buf][kk][tm]);
            *(float4*)(a + 4) = *(const float4*)(&As[buf][kk][tm + 4]);
            *(float4*)(b)     = *(const float4*)(&Bs[buf][kk][tn]);
            *(float4*)(b + 4) = *(const float4*)(&Bs[buf][kk][tn + 4]);
#pragma unroll
            for (int i = 0; i < 8; i++)
#pragma unroll
                for (int j = 0; j < 8; j++)
                    acc[i][j] = fmaf(a[i], b[j], acc[i][j]);
        }

        if (hasNext) {
            STS_TILE(buf ^ 1);
            __syncthreads();
            buf ^= 1;
        }
    }
#undef LDG_TILE
#undef STS_TILE

#pragma unroll
    for (int i = 0; i < 8; i++) {
        int m = m0 + tm + i;
#pragma unroll
        for (int j = 0; j < 8; j++) {
            int n = n0 + tn + j;
            if (n < N) {
                float v = acc[i][j];
                if (EPI == 1) v = tanhf(v);
                else if (EPI == 2) v = fmaxf(v, 0.f);
                else if (EPI == 3) v = expf(-expf(bias[n] + v));
                Cmat[(size_t)m * N + n] = v;
            }
        }
    }
}

// ==========================================================================
// Fused token-mix v3: 64-row blocks, weights in registers once per f.
// grid (NR_/64, C_/128), 256 thr. Per f: wreg[32] loaded from global once,
// t5 staged for all 64 rows, 32 row-pair iterations of pure fma.
// f=0 -> xw (fp32); f=1..4 -> bf16 hi/lo (slots 0=k,1=v,2=r,3=g)
// ==========================================================================
__global__ void __launch_bounds__(256, 2)
k_mix(const float* __restrict__ x, const float* __restrict__ xx,
      const float* __restrict__ t5, const float* __restrict__ w2,
      const float* __restrict__ ma0, const float* __restrict__ ma1,
      const float* __restrict__ ma2, const float* __restrict__ ma3,
      const float* __restrict__ ma4,
      float* __restrict__ xw,
      __nv_bfloat16* __restrict__ acthi, __nv_bfloat16* __restrict__ actlo)
{
    const int r0  = blockIdx.x * 64;
    const int c0  = blockIdx.y * 128;
    const int tid = threadIdx.x;
    const int cl  = tid & 127;
    const int rh  = tid >> 7;

    __shared__ __align__(16) float tsh[64][36];   // row stride 144B (16B aligned)

    float mfv[5];
    mfv[0] = ma0[c0 + cl]; mfv[1] = ma1[c0 + cl]; mfv[2] = ma2[c0 + cl];
    mfv[3] = ma3[c0 + cl]; mfv[4] = ma4[c0 + cl];

    for (int f = 0; f < 5; f++) {
        // stage t5[r0..r0+64][f*32..f*32+32] -> tsh
#pragma unroll
        for (int l = 0; l < 8; l++) {
            int e = tid + l * 256;                 // 0..2047
            tsh[e >> 5][e & 31] = t5[(size_t)(r0 + (e >> 5)) * 160 + f * 32 + (e & 31)];
        }
        // weights for this f, column cl -> registers (coalesced LDG)
        float wreg[32];
#pragma unroll
        for (int rr = 0; rr < 32; rr++)
            wreg[rr] = w2[(size_t)(f * 32 + rr) * C_ + c0 + cl];
        __syncthreads();

        const float mf = mfv[f];
        const size_t slotoff = (size_t)(f - 1) * NC_;

#pragma unroll 4
        for (int rp = 0; rp < 32; rp++) {
            const int row = rp * 2 + rh;
            size_t idx = (size_t)(r0 + row) * C_ + c0 + cl;
            float xv  = x[idx];
            float xxv = xx[idx];
            const float4* trow = (const float4*)(&tsh[row][0]);
            float a = 0.f;
#pragma unroll
            for (int q = 0; q < 8; q++) {
                float4 t4 = trow[q];
                a = fmaf(t4.x, wreg[4 * q + 0], a);
                a = fmaf(t4.y, wreg[4 * q + 1], a);
                a = fmaf(t4.z, wreg[4 * q + 2], a);
                a = fmaf(t4.w, wreg[4 * q + 3], a);
            }
            float val = fmaf(xxv, mf + a, xv);
            if (f == 0) {
                xw[idx] = val;
            } else {
                __nv_bfloat16 h = __float2bfloat16(val);
                acthi[slotoff + idx] = h;
                actlo[slotoff + idx] = __float2bfloat16(val - __bfloat162float(h));
            }
        }
        __syncthreads();
    }
}

// ==========================================================================
// ruk[row,h] = sum_j r*u*k
// ==========================================================================
__global__ void k_ruk(const float* __restrict__ r, const float* __restrict__ k,
                      const float* __restrict__ u, float* __restrict__ ruk)
{
    const int row = blockIdx.x;
    const int c   = threadIdx.x;
    const int h   = c >> 6;
    const int j   = c & 63;
    size_t idx = (size_t)row * C_ + c;
    float p = r[idx] * u[c] * k[idx];
#pragma unroll
    for (int off = 16; off; off >>= 1) p += __shfl_xor_sync(0xffffffffu, p, off);
    __shared__ float ws[24];
    if ((c & 31) == 0) ws[c >> 5] = p;
    __syncthreads();
    if (j == 0) ruk[(size_t)row * H_ + h] = ws[2 * h] + ws[2 * h + 1];
}

// ==========================================================================
// WKV6 recurrence (256 threads, j split in quarters)
// ==========================================================================
__global__ void __launch_bounds__(256)
k_wkv(const float* __restrict__ r, const float* __restrict__ k,
      const float* __restrict__ v, const float* __restrict__ wd,
      const float* __restrict__ ruk, float* __restrict__ y)
{
    const int bh = blockIdx.x;
    const int b  = bh / H_;
    const int h  = bh % H_;
    const int tid = threadIdx.x;
    const int i  = tid & 63;
    const int q  = tid >> 6;

    __shared__ __align__(16) float sr[64];
    __shared__ __align__(16) float sk[64];
    __shared__ __align__(16) float sw[64];
    __shared__ __align__(16) float sv[64];
    __shared__ float part[3][64];

    float S[16];
#pragma unroll
    for (int jj = 0; jj < 16; jj++) S[jj] = 0.f;

    const size_t base  = (size_t)b * T_ * C_ + h * 64;
    const size_t rbase = (size_t)b * T_ * H_ + h;

    const float* mysrc = (q == 0) ? r : (q == 1) ? k : (q == 2) ? wd : v;
    float cur = mysrc[base + i];

    for (int t = 0; t < T_; t++) {
        if (q == 0)      sr[i] = cur;
        else if (q == 1) sk[i] = cur;
        else if (q == 2) sw[i] = cur;
        else             sv[i] = cur;
        __syncthreads();

        float nxt = cur;
        if (t + 1 < T_) nxt = mysrc[base + (size_t)(t + 1) * C_ + i];

        const float vi = sv[i];
        float yp = 0.f;
#pragma unroll
        for (int g4 = 0; g4 < 4; g4++) {
            float4 r4 = *(const float4*)(sr + q * 16 + g4 * 4);
            float4 k4 = *(const float4*)(sk + q * 16 + g4 * 4);
            float4 w4 = *(const float4*)(sw + q * 16 + g4 * 4);
            float kv;
            kv = k4.x * vi; yp = fmaf(r4.x, S[4*g4+0], yp); S[4*g4+0] = fmaf(w4.x, S[4*g4+0], kv);
            kv = k4.y * vi; yp = fmaf(r4.y, S[4*g4+1], yp); S[4*g4+1] = fmaf(w4.y, S[4*g4+1], kv);
            kv = k4.z * vi; yp = fmaf(r4.z, S[4*g4+2], yp); S[4*g4+2] = fmaf(w4.z, S[4*g4+2], kv);
            kv = k4.w * vi; yp = fmaf(r4.w, S[4*g4+3], yp); S[4*g4+3] = fmaf(w4.w, S[4*g4+3], kv);
        }
        if (q) part[q - 1][i] = yp;
        __syncthreads();

        if (q == 0) {
            float yv = yp + part[0][i] + part[1][i] + part[2][i];
            yv = fmaf(ruk[rbase + (size_t)t * H_], vi, yv);
            y[base + (size_t)t * C_ + i] = yv;
        }
        cur = nxt;
    }
}

// ==========================================================================
// GroupNorm * g -> bf16 hi/lo split directly (for the W_o GEMM)
// ==========================================================================
__global__ void k_gnorm(const float* __restrict__ y, const float* __restrict__ gbuf,
                        const float* __restrict__ lnw, const float* __restrict__ lnb,
                        __nv_bfloat16* __restrict__ hi, __nv_bfloat16* __restrict__ lo)
{
    const int row = blockIdx.x;
    const int c   = threadIdx.x;
    size_t idx = (size_t)row * C_ + c;
    float v = y[idx];
    float s = v, s2 = v * v;
#pragma unroll
    for (int off = 16; off; off >>= 1) {
        s  += __shfl_xor_sync(0xffffffffu, s,  off);
        s2 += __shfl_xor_sync(0xffffffffu, s2, off);
    }
    __shared__ float as[24], as2[24];
    if ((c & 31) == 0) { as[c >> 5] = s; as2[c >> 5] = s2; }
    __syncthreads();
    const int g = c >> 6;
    float sum  = as[2 * g]  + as[2 * g + 1];
    float sum2 = as2[2 * g] + as2[2 * g + 1];
    float mu   = sum * (1.f / 64.f);
    float var  = sum2 * (1.f / 64.f) - mu * mu;
    float nv   = (v - mu) * rsqrtf(var + 1e-5f);
    float val  = fmaf(nv, lnw[c], lnb[c]) * gbuf[idx];
    __nv_bfloat16 h = __float2bfloat16(val);
    hi[idx] = h;
    lo[idx] = __float2bfloat16(val - __bfloat162float(h));
}

// ==========================================================================
// Host launcher
// ==========================================================================
extern "C" void kernel_launch(void* const* d_in, const int* in_sizes, int n_in,
                              void* d_out, int out_size)
{
    const float* x     = (const float*)d_in[0];
    const float* W_r   = (const float*)d_in[1];
    const float* W_k   = (const float*)d_in[2];
    const float* W_v   = (const float*)d_in[3];
    const float* W_g   = (const float*)d_in[4];
    const float* W_o   = (const float*)d_in[5];
    const float* maa_x = (const float*)d_in[6];
    const float* maa_w = (const float*)d_in[7];
    const float* maa_k = (const float*)d_in[8];
    const float* maa_v = (const float*)d_in[9];
    const float* maa_r = (const float*)d_in[10];
    const float* maa_g = (const float*)d_in[11];
    const float* maa_w1= (const float*)d_in[12];
    const float* maa_w2= (const float*)d_in[13];
    const float* tdec  = (const float*)d_in[14];
    const float* dec_w1= (const float*)d_in[15];
    const float* dec_w2= (const float*)d_in[16];
    const float* faaaa = (const float*)d_in[17];
    const float* ln_w  = (const float*)d_in[18];
    const float* ln_b  = (const float*)d_in[19];
    (void)in_sizes; (void)n_in; (void)out_size;

    float* S = nullptr;
    cudaGetSymbolAddress((void**)&S, g_scratch);
    __nv_bfloat16 *acthi = nullptr, *actlo = nullptr, *w5hi = nullptr, *w5lo = nullptr;
    cudaGetSymbolAddress((void**)&acthi, g_acthi);
    cudaGetSymbolAddress((void**)&actlo, g_actlo);
    cudaGetSymbolAddress((void**)&w5hi, g_w5hi);
    cudaGetSymbolAddress((void**)&w5lo, g_w5lo);

    float* xx   = S + OFF_XX;
    float* xxx  = S + OFF_XXX;
    float* t5   = S + OFF_T5;
    float* xw   = S + OFF_XW;
    float* rb   = S + OFF_R;
    float* kb   = S + OFF_K;
    float* vb   = S + OFF_V;
    float* gb   = S + OFF_G;
    float* h1   = S + OFF_H1;
    float* wdec = S + OFF_WDEC;
    float* yb   = S + OFF_Y;
    float* ruk  = S + OFF_RUK;
    float* outp = (float*)d_out;

    const dim3 gTC(C_ / 128, NR_ / 128);   // (6, 64)

    // 0. split all 5 weights
    k_split5<<<(unsigned)(5 * WSZ_ / 4 / 256), 256>>>(W_r, W_k, W_v, W_g, W_o, w5hi, w5lo);

    // 1. shift + xxx (float4)
    k_shift<<<(unsigned)(NC_ / 4 / 256), 256>>>(x, maa_x, xx, xxx);

    // 2. t5 = tanh(xxx @ maa_w1)
    k_gemm<1, false><<<dim3(2, NR_ / 128), 256>>>(xxx, maa_w1, t5, NR_, 160, C_, nullptr);

    // 3. fused token mix -> xw fp32 + bf16 hi/lo for k,v,r,g
    k_mix<<<dim3(NR_ / 64, C_ / 128), 256>>>(x, xx, t5, maa_w2,
                                             maa_w, maa_k, maa_v, maa_r, maa_g,
                                             xw, acthi, actlo);

    // 4. big NT GEMMs (bf16-split mma.sync). act slots: 0=k,1=v,2=r,3=g
    k_gemm_mma<<<gTC, 256>>>(acthi + 2 * NC_, actlo + 2 * NC_,
                             w5hi + 0 * WSZ_, w5lo + 0 * WSZ_, rb, 0);
    k_gemm_mma<<<gTC, 256>>>(acthi + 0 * NC_, actlo + 0 * NC_,
                             w5hi + 1 * WSZ_, w5lo + 1 * WSZ_, kb, 0);
    k_gemm_mma<<<gTC, 256>>>(acthi + 1 * NC_, actlo + 1 * NC_,
                             w5hi + 2 * WSZ_, w5lo + 2 * WSZ_, vb, 0);
    k_gemm_mma<<<gTC, 256>>>(acthi + 3 * NC_, actlo + 3 * NC_,
                             w5hi + 3 * WSZ_, w5lo + 3 * WSZ_, gb, 1);  // relu

    // 5. decay path (small fp32 GEMMs)
    k_gemm<1, false><<<dim3(1, NR_ / 128), 256>>>(xw, dec_w1, h1, NR_, 64, C_, nullptr);
    k_gemm<3, false><<<dim3(C_ / 128, NR_ / 128), 256>>>(h1, dec_w2, wdec, NR_, C_, 64, tdec);

    // 6. wkv recurrence
    k_ruk<<<NR_, C_>>>(rb, kb, faaaa, ruk);
    k_wkv<<<B_ * H_, 256>>>(rb, kb, vb, wdec, ruk, yb);

    // 7. groupnorm * g -> bf16 pair (reuse act slot 0)
    k_gnorm<<<NR_, C_>>>(yb, gb, ln_w, ln_b, acthi, actlo);

    // 8. out = yn @ W_o^T
    k_gemm_mma<<<gTC, 256>>>(acthi, actlo,
                             w5hi + 4 * WSZ_, w5lo + 4 * WSZ_, outp, 0);
}

// round 10
// speedup vs baseline: 1.0552x; 1.0180x over previous
#include <cuda_runtime.h>
#include <cuda_bf16.h>
#include <math.h>
#include <stdint.h>

// ---------------- problem constants (fixed shapes) ----------------
#define B_   8
#define T_   1024
#define C_   768
#define H_   12
#define HS_  64
#define PH_  32
#define PW_  32
#define NR_  (B_ * T_)          // 8192 rows
#define NC_  ((size_t)NR_ * C_) // 6291456 elems
#define WSZ_ ((size_t)C_ * C_)  // 589824

// ---------------- scratch ----------------
__device__ __align__(16) float g_scratch[10 * NC_ + (size_t)NR_ * 160 + (size_t)NR_ * 64 + (size_t)NR_ * H_];
__device__ __align__(16) __nv_bfloat16 g_acthi[4 * NC_];   // slots: 0=k,1=v,2=r,3=g
__device__ __align__(16) __nv_bfloat16 g_actlo[4 * NC_];
__device__ __align__(16) __nv_bfloat16 g_w5hi[5 * WSZ_];   // W_r,W_k,W_v,W_g,W_o
__device__ __align__(16) __nv_bfloat16 g_w5lo[5 * WSZ_];

#define OFF_XX   ((size_t)0)
#define OFF_XXX  (OFF_XX  + NC_)
#define OFF_T5   (OFF_XXX + NC_)
#define OFF_XW   (OFF_T5  + (size_t)NR_ * 160)
#define OFF_R    (OFF_XW  + NC_)
#define OFF_K    (OFF_R   + NC_)
#define OFF_V    (OFF_K   + NC_)
#define OFF_G    (OFF_V   + NC_)
#define OFF_H1   (OFF_G   + NC_)
#define OFF_WDEC (OFF_H1  + (size_t)NR_ * 64)
#define OFF_Y    (OFF_WDEC+ NC_)
#define OFF_RUK  (OFF_Y   + NC_)

// ========================= helpers ==========================
__device__ __forceinline__ uint32_t smem_u32(const void* p) {
    uint32_t a;
    asm("{ .reg .u64 t; cvta.to.shared.u64 t, %1; cvt.u32.u64 %0, t; }" : "=r"(a) : "l"(p));
    return a;
}
__device__ __forceinline__ void ldsm_x4(uint32_t* r, uint32_t addr) {
    asm volatile("ldmatrix.sync.aligned.m8n8.x4.shared.b16 {%0,%1,%2,%3}, [%4];"
                 : "=r"(r[0]), "=r"(r[1]), "=r"(r[2]), "=r"(r[3]) : "r"(addr));
}
__device__ __forceinline__ void mma_bf16(float* c, const uint32_t* a, uint32_t b0, uint32_t b1) {
    asm volatile("mma.sync.aligned.m16n8k16.row.col.f32.bf16.bf16.f32 "
                 "{%0,%1,%2,%3}, {%4,%5,%6,%7}, {%8,%9}, {%0,%1,%2,%3};"
                 : "+f"(c[0]), "+f"(c[1]), "+f"(c[2]), "+f"(c[3])
                 : "r"(a[0]), "r"(a[1]), "r"(a[2]), "r"(a[3]), "r"(b0), "r"(b1));
}

// ==========================================================================
// bf16-split tensor-core GEMM via mma.sync (proven version, unchanged)
// ==========================================================================
#define PLANE_   2080
#define ATILE_   (4 * PLANE_)
#define BUFSZ_   (2 * ATILE_)

__global__ void __launch_bounds__(256, 2)
k_gemm_mma(const __nv_bfloat16* __restrict__ Ahi, const __nv_bfloat16* __restrict__ Alo,
           const __nv_bfloat16* __restrict__ Whi, const __nv_bfloat16* __restrict__ Wlo,
           float* __restrict__ Cmat, int doRelu)
{
    __shared__ __align__(16) char sm[2][BUFSZ_];

    const int tid  = threadIdx.x;
    const int warp = tid >> 5;
    const int lane = tid & 31;
    const int m0 = blockIdx.y * 128;
    const int n0 = blockIdx.x * 128;
    const int wm = warp >> 2;
    const int wn = warp & 3;

    float acc[4][4][4];
#pragma unroll
    for (int i = 0; i < 4; i++)
#pragma unroll
        for (int j = 0; j < 4; j++)
#pragma unroll
            for (int q = 0; q < 4; q++) acc[i][j][q] = 0.f;

    const int ldrow = tid >> 1;
    const int ldcb  = (tid & 1) * 2;

    uint4 ra[2], rb[2];

    const uint32_t sb = smem_u32(sm);
    const int lgrp = lane >> 3;
    const int lrl  = lane & 7;

#define LDG_T(c_)                                                               \
    {                                                                           \
        const int seg_ = (c_) / 24;                                             \
        const int kc_  = ((c_) % 24) * 32;                                      \
        const __nv_bfloat16* Ag = (seg_ == 1) ? Alo : Ahi;                      \
        const __nv_bfloat16* Bg = (seg_ == 2) ? Wlo : Whi;                      \
        const __nv_bfloat16* ap = Ag + (size_t)(m0 + ldrow) * C_ + kc_ + ldcb * 8; \
        const __nv_bfloat16* bp = Bg + (size_t)(n0 + ldrow) * C_ + kc_ + ldcb * 8; \
        ra[0] = *(const uint4*)ap; ra[1] = *(const uint4*)(ap + 8);             \
        rb[0] = *(const uint4*)bp; rb[1] = *(const uint4*)(bp + 8);             \
    }

#define STS_T(buf_)                                                             \
    {                                                                           \
        char* b_ = sm[buf_];                                                    \
        *(uint4*)(b_ + (ldcb + 0) * PLANE_ + ldrow * 16) = ra[0];               \
        *(uint4*)(b_ + (ldcb + 1) * PLANE_ + ldrow * 16) = ra[1];               \
        *(uint4*)(b_ + ATILE_ + (ldcb + 0) * PLANE_ + ldrow * 16) = rb[0];      \
        *(uint4*)(b_ + ATILE_ + (ldcb + 1) * PLANE_ + ldrow * 16) = rb[1];      \
    }

    LDG_T(0);
    STS_T(0);
    __syncthreads();

    for (int c = 0; c < 72; c++) {
        const int buf = c & 1;
        const bool hasNext = (c + 1 < 72);
        if (hasNext) LDG_T(c + 1);

        const uint32_t abase = sb + buf * BUFSZ_;
        const uint32_t bbase = abase + ATILE_;

#pragma unroll
        for (int kk = 0; kk < 2; kk++) {
            uint32_t afr[4][4], bfr[2][4];
#pragma unroll
            for (int mt = 0; mt < 4; mt++) {
                int row   = wm * 64 + mt * 16 + (lgrp & 1) * 8 + lrl;
                int chunk = kk * 2 + (lgrp >> 1);
                ldsm_x4(afr[mt], abase + chunk * PLANE_ + row * 16);
            }
#pragma unroll
            for (int nt = 0; nt < 2; nt++) {
                int nr    = wn * 32 + nt * 16 + (lgrp >> 1) * 8 + lrl;
                int chunk = kk * 2 + (lgrp & 1);
                ldsm_x4(bfr[nt], bbase + chunk * PLANE_ + nr * 16);
            }
#pragma unroll
            for (int mt = 0; mt < 4; mt++)
#pragma unroll
                for (int ng = 0; ng < 4; ng++)
                    mma_bf16(acc[mt][ng], afr[mt], bfr[ng >> 1][(ng & 1) * 2 + 0],
                             bfr[ng >> 1][(ng & 1) * 2 + 1]);
        }

        if (hasNext) {
            STS_T(buf ^ 1);
            __syncthreads();
        }
    }
#undef LDG_T
#undef STS_T

#pragma unroll
    for (int mt = 0; mt < 4; mt++) {
        const int r0 = m0 + wm * 64 + mt * 16 + (lane >> 2);
#pragma unroll
        for (int ng = 0; ng < 4; ng++) {
            const int col = n0 + wn * 32 + ng * 8 + (lane & 3) * 2;
            float c0 = acc[mt][ng][0], c1 = acc[mt][ng][1];
            float c2 = acc[mt][ng][2], c3 = acc[mt][ng][3];
            if (doRelu) {
                c0 = fmaxf(c0, 0.f); c1 = fmaxf(c1, 0.f);
                c2 = fmaxf(c2, 0.f); c3 = fmaxf(c3, 0.f);
            }
            *(float2*)(Cmat + (size_t)r0 * C_ + col)       = make_float2(c0, c1);
            *(float2*)(Cmat + (size_t)(r0 + 8) * C_ + col) = make_float2(c2, c3);
        }
    }
}

// ==========================================================================
// Split all five weight matrices into bf16 hi/lo once (float4 vectorized).
// ==========================================================================
__global__ void __launch_bounds__(256)
k_split5(const float* __restrict__ w0, const float* __restrict__ w1,
         const float* __restrict__ w2, const float* __restrict__ w3,
         const float* __restrict__ w4,
         __nv_bfloat16* __restrict__ hi, __nv_bfloat16* __restrict__ lo)
{
    size_t i4 = (size_t)blockIdx.x * blockDim.x + threadIdx.x;
    size_t idx = i4 * 4;
    int sel = (int)(idx / WSZ_);
    size_t off = idx % WSZ_;
    const float* src = (sel == 0) ? w0 : (sel == 1) ? w1 : (sel == 2) ? w2 : (sel == 3) ? w3 : w4;
    float4 a = *(const float4*)(src + off);
    __nv_bfloat16 h0 = __float2bfloat16(a.x);
    __nv_bfloat16 h1 = __float2bfloat16(a.y);
    __nv_bfloat16 h2 = __float2bfloat16(a.z);
    __nv_bfloat16 h3 = __float2bfloat16(a.w);
    __nv_bfloat162 hp0, hp1, lp0, lp1;
    hp0.x = h0; hp0.y = h1; hp1.x = h2; hp1.y = h3;
    lp0.x = __float2bfloat16(a.x - __bfloat162float(h0));
    lp0.y = __float2bfloat16(a.y - __bfloat162float(h1));
    lp1.x = __float2bfloat16(a.z - __bfloat162float(h2));
    lp1.y = __float2bfloat16(a.w - __bfloat162float(h3));
    *(uint2*)(hi + idx) = make_uint2(*(uint32_t*)&hp0, *(uint32_t*)&hp1);
    *(uint2*)(lo + idx) = make_uint2(*(uint32_t*)&lp0, *(uint32_t*)&lp1);
}

// ==========================================================================
// Kernel 1: q-shift (float4) -> xx = shift(x) - x ; xxx = x + xx * maa_x
// ==========================================================================
__global__ void __launch_bounds__(256)
k_shift(const float* __restrict__ x, const float* __restrict__ maa_x,
        float* __restrict__ xx, float* __restrict__ xxx)
{
    size_t i4 = (size_t)blockIdx.x * blockDim.x + threadIdx.x;
    size_t idx = i4 * 4;
    int c  = (int)(idx % C_);
    int bt = (int)(idx / C_);
    int t  = bt % T_;
    int w  = t % PW_;
    int h  = t / PW_;
    int quarter = (c & (HS_ - 1)) >> 4;

    float4 src = make_float4(0.f, 0.f, 0.f, 0.f);
    if (quarter == 0)      { if (w > 0)       src = *(const float4*)(x + idx - C_); }
    else if (quarter == 1) { if (w < PW_ - 1) src = *(const float4*)(x + idx + C_); }
    else if (quarter == 2) { if (h > 0)       src = *(const float4*)(x + idx - PW_ * C_); }
    else                   { if (h < PH_ - 1) src = *(const float4*)(x + idx + PW_ * C_); }

    float4 xv = *(const float4*)(x + idx);
    float4 mv = *(const float4*)(maa_x + c);
    float4 d, o;
    d.x = src.x - xv.x; d.y = src.y - xv.y; d.z = src.z - xv.z; d.w = src.w - xv.w;
    o.x = fmaf(d.x, mv.x, xv.x); o.y = fmaf(d.y, mv.y, xv.y);
    o.z = fmaf(d.z, mv.z, xv.z); o.w = fmaf(d.w, mv.w, xv.w);
    *(float4*)(xx + idx)  = d;
    *(float4*)(xxx + idx) = o;
}

// ==========================================================================
// Pipelined tiled fp32 GEMM (small N/K GEMMs only)
// ==========================================================================
template<int EPI, bool BNT>
__global__ void __launch_bounds__(256, 2)
k_gemm(const float* __restrict__ A, const float* __restrict__ B,
       float* __restrict__ Cmat, int M, int N, int K, const float* __restrict__ bias)
{
    __shared__ float As[2][16][132];
    __shared__ float Bs[2][16][132];

    const int m0   = blockIdx.y * 128;
    const int n0   = blockIdx.x * 128;
    const int tid  = threadIdx.x;
    const int warp = tid >> 5;
    const int lane = tid & 31;
    const int tm   = (warp >> 2) * 64 + (lane >> 2) * 8;
    const int tn   = (warp & 3) * 32 + (lane & 3) * 8;

    float acc[8][8];
#pragma unroll
    for (int i = 0; i < 8; i++)
#pragma unroll
        for (int j = 0; j < 8; j++) acc[i][j] = 0.f;

    float4 aR[2], bR[2];

#define LDG_TILE(k0_)                                                          \
    {                                                                          \
        _Pragma("unroll")                                                      \
        for (int l = 0; l < 2; l++) {                                          \
            int e  = tid + l * 256;                                            \
            int am = e >> 2;                                                   \
            int ak = (e & 3) * 4;                                              \
            aR[l] = *(const float4*)(A + (size_t)(m0 + am) * K + (k0_) + ak);  \
            if (BNT) {                                                         \
                int bn = e >> 2;                                               \
                int bk = (e & 3) * 4;                                          \
                bR[l] = make_float4(0.f, 0.f, 0.f, 0.f);                       \
                if (n0 + bn < N)                                               \
                    bR[l] = *(const float4*)(B + (size_t)(n0 + bn) * K + (k0_) + bk); \
            } else {                                                           \
                int bk = e >> 5;                                               \
                int bn = (e & 31) * 4;                                         \
                bR[l] = make_float4(0.f, 0.f, 0.f, 0.f);                       \
                if (n0 + bn < N)                                               \
                    bR[l] = *(const float4*)(B + (size_t)((k0_) + bk) * N + n0 + bn); \
            }                                                                  \
        }                                                                      \
    }

#define STS_TILE(buf_)                                                         \
    {                                                                          \
        _Pragma("unroll")                                                      \
        for (int l = 0; l < 2; l++) {                                          \
            int e  = tid + l * 256;                                            \
            int am = e >> 2;                                                   \
            int ak = (e & 3) * 4;                                              \
            As[buf_][ak + 0][am] = aR[l].x; As[buf_][ak + 1][am] = aR[l].y;    \
            As[buf_][ak + 2][am] = aR[l].z; As[buf_][ak + 3][am] = aR[l].w;    \
            if (BNT) {                                                         \
                int bn = e >> 2;                                               \
                int bk = (e & 3) * 4;                                          \
                Bs[buf_][bk + 0][bn] = bR[l].x; Bs[buf_][bk + 1][bn] = bR[l].y;\
                Bs[buf_][bk + 2][bn] = bR[l].z; Bs[buf_][bk + 3][bn] = bR[l].w;\
            } else {                                                           \
                int bk = e >> 5;                                               \
                int bn = (e & 31) * 4;                                         \
                *(float4*)(&Bs[buf_][bk][bn]) = bR[l];                         \
            }                                                                  \
        }                                                                      \
    }

    LDG_TILE(0);
    STS_TILE(0);
    __syncthreads();

    int buf = 0;
    for (int k0 = 0; k0 < K; k0 += 16) {
        const bool hasNext = (k0 + 16 < K);
        if (hasNext) LDG_TILE(k0 + 16);

#pragma unroll
        for (int kk = 0; kk < 16; kk++) {
            float a[8], b[8];
            *(float4*)(a)     = *(const float4*)(&As[buf][kk][tm]);
            *(float4*)(a + 4) = *(const float4*)(&As[buf][kk][tm + 4]);
            *(float4*)(b)     = *(const float4*)(&Bs[buf][kk][tn]);
            *(float4*)(b + 4) = *(const float4*)(&Bs[buf][kk][tn + 4]);
#pragma unroll
            for (int i = 0; i < 8; i++)
#pragma unroll
                for (int j = 0; j < 8; j++)
                    acc[i][j] = fmaf(a[i], b[j], acc[i][j]);
        }

        if (hasNext) {
            STS_TILE(buf ^ 1);
            __syncthreads();
            buf ^= 1;
        }
    }
#undef LDG_TILE
#undef STS_TILE

#pragma unroll
    for (int i = 0; i < 8; i++) {
        int m = m0 + tm + i;
#pragma unroll
        for (int j = 0; j < 8; j++) {
            int n = n0 + tn + j;
            if (n < N) {
                float v = acc[i][j];
                if (EPI == 1) v = tanhf(v);
                else if (EPI == 2) v = fmaxf(v, 0.f);
                else if (EPI == 3) v = expf(-expf(bias[n] + v));
                Cmat[(size_t)m * N + n] = v;
            }
        }
    }
}

// ==========================================================================
// Fused token-mix v4: 64-row blocks, column PAIRS per thread.
// grid (NR_/64, C_/128), 256 thr: thread owns 2 adjacent cols, 4 row-phases.
// Per f: wreg float2[32] from global (once), t5 staged in smem, 16 rows/thread.
// f=0 -> xw (float2); f=1..4 -> bf16x2 hi/lo 32-bit stores.
// ==========================================================================
__global__ void __launch_bounds__(256, 2)
k_mix(const float* __restrict__ x, const float* __restrict__ xx,
      const float* __restrict__ t5, const float* __restrict__ w2,
      const float* __restrict__ ma0, const float* __restrict__ ma1,
      const float* __restrict__ ma2, const float* __restrict__ ma3,
      const float* __restrict__ ma4,
      float* __restrict__ xw,
      __nv_bfloat16* __restrict__ acthi, __nv_bfloat16* __restrict__ actlo)
{
    const int r0  = blockIdx.x * 64;
    const int c0  = blockIdx.y * 128;
    const int tid = threadIdx.x;
    const int cp  = (tid & 63) * 2;      // column pair base within 128
    const int rh  = tid >> 6;            // 0..3 row phase

    __shared__ __align__(16) float tsh[64][36];   // row stride 144B

    float2 mfv[5];
    mfv[0] = *(const float2*)(ma0 + c0 + cp);
    mfv[1] = *(const float2*)(ma1 + c0 + cp);
    mfv[2] = *(const float2*)(ma2 + c0 + cp);
    mfv[3] = *(const float2*)(ma3 + c0 + cp);
    mfv[4] = *(const float2*)(ma4 + c0 + cp);

    for (int f = 0; f < 5; f++) {
        // stage t5[r0..r0+64][f*32..f*32+32] -> tsh
#pragma unroll
        for (int l = 0; l < 8; l++) {
            int e = tid + l * 256;                 // 0..2047
            tsh[e >> 5][e & 31] = t5[(size_t)(r0 + (e >> 5)) * 160 + f * 32 + (e & 31)];
        }
        // weights for this f, 2 columns -> registers (coalesced float2 LDG)
        float2 wreg[32];
#pragma unroll
        for (int rr = 0; rr < 32; rr++)
            wreg[rr] = *(const float2*)(w2 + (size_t)(f * 32 + rr) * C_ + c0 + cp);
        __syncthreads();

        const float2 mf = mfv[f];
        const size_t slotoff = (size_t)(f - 1) * NC_;
        size_t idx = (size_t)(r0 + rh) * C_ + c0 + cp;

#pragma unroll 4
        for (int it = 0; it < 16; it++) {
            const int row = rh + it * 4;
            float2 xv  = *(const float2*)(x + idx);
            float2 xxv = *(const float2*)(xx + idx);
            const float4* trow = (const float4*)(&tsh[row][0]);
            float a0 = 0.f, a1 = 0.f;
#pragma unroll
            for (int q = 0; q < 8; q++) {
                float4 t4 = trow[q];
                float2 w0 = wreg[4 * q + 0], w1 = wreg[4 * q + 1];
                float2 w2r = wreg[4 * q + 2], w3 = wreg[4 * q + 3];
                a0 = fmaf(t4.x, w0.x, a0); a1 = fmaf(t4.x, w0.y, a1);
                a0 = fmaf(t4.y, w1.x, a0); a1 = fmaf(t4.y, w1.y, a1);
                a0 = fmaf(t4.z, w2r.x, a0); a1 = fmaf(t4.z, w2r.y, a1);
                a0 = fmaf(t4.w, w3.x, a0); a1 = fmaf(t4.w, w3.y, a1);
            }
            float v0 = fmaf(xxv.x, mf.x + a0, xv.x);
            float v1 = fmaf(xxv.y, mf.y + a1, xv.y);
            if (f == 0) {
                *(float2*)(xw + idx) = make_float2(v0, v1);
            } else {
                __nv_bfloat162 hp, lp;
                hp.x = __float2bfloat16(v0);
                hp.y = __float2bfloat16(v1);
                lp.x = __float2bfloat16(v0 - __bfloat162float(hp.x));
                lp.y = __float2bfloat16(v1 - __bfloat162float(hp.y));
                *(uint32_t*)(acthi + slotoff + idx) = *(uint32_t*)&hp;
                *(uint32_t*)(actlo + slotoff + idx) = *(uint32_t*)&lp;
            }
            idx += 4 * C_;
        }
        __syncthreads();
    }
}

// ==========================================================================
// ruk[row,h] = sum_j r*u*k
// ==========================================================================
__global__ void k_ruk(const float* __restrict__ r, const float* __restrict__ k,
                      const float* __restrict__ u, float* __restrict__ ruk)
{
    const int row = blockIdx.x;
    const int c   = threadIdx.x;
    const int h   = c >> 6;
    const int j   = c & 63;
    size_t idx = (size_t)row * C_ + c;
    float p = r[idx] * u[c] * k[idx];
#pragma unroll
    for (int off = 16; off; off >>= 1) p += __shfl_xor_sync(0xffffffffu, p, off);
    __shared__ float ws[24];
    if ((c & 31) == 0) ws[c >> 5] = p;
    __syncthreads();
    if (j == 0) ruk[(size_t)row * H_ + h] = ws[2 * h] + ws[2 * h + 1];
}

// ==========================================================================
// WKV6 recurrence (256 threads, j split in quarters)
// ==========================================================================
__global__ void __launch_bounds__(256)
k_wkv(const float* __restrict__ r, const float* __restrict__ k,
      const float* __restrict__ v, const float* __restrict__ wd,
      const float* __restrict__ ruk, float* __restrict__ y)
{
    const int bh = blockIdx.x;
    const int b  = bh / H_;
    const int h  = bh % H_;
    const int tid = threadIdx.x;
    const int i  = tid & 63;
    const int q  = tid >> 6;

    __shared__ __align__(16) float sr[64];
    __shared__ __align__(16) float sk[64];
    __shared__ __align__(16) float sw[64];
    __shared__ __align__(16) float sv[64];
    __shared__ float part[3][64];

    float S[16];
#pragma unroll
    for (int jj = 0; jj < 16; jj++) S[jj] = 0.f;

    const size_t base  = (size_t)b * T_ * C_ + h * 64;
    const size_t rbase = (size_t)b * T_ * H_ + h;

    const float* mysrc = (q == 0) ? r : (q == 1) ? k : (q == 2) ? wd : v;
    float cur = mysrc[base + i];

    for (int t = 0; t < T_; t++) {
        if (q == 0)      sr[i] = cur;
        else if (q == 1) sk[i] = cur;
        else if (q == 2) sw[i] = cur;
        else             sv[i] = cur;
        __syncthreads();

        float nxt = cur;
        if (t + 1 < T_) nxt = mysrc[base + (size_t)(t + 1) * C_ + i];

        const float vi = sv[i];
        float yp = 0.f;
#pragma unroll
        for (int g4 = 0; g4 < 4; g4++) {
            float4 r4 = *(const float4*)(sr + q * 16 + g4 * 4);
            float4 k4 = *(const float4*)(sk + q * 16 + g4 * 4);
            float4 w4 = *(const float4*)(sw + q * 16 + g4 * 4);
            float kv;
            kv = k4.x * vi; yp = fmaf(r4.x, S[4*g4+0], yp); S[4*g4+0] = fmaf(w4.x, S[4*g4+0], kv);
            kv = k4.y * vi; yp = fmaf(r4.y, S[4*g4+1], yp); S[4*g4+1] = fmaf(w4.y, S[4*g4+1], kv);
            kv = k4.z * vi; yp = fmaf(r4.z, S[4*g4+2], yp); S[4*g4+2] = fmaf(w4.z, S[4*g4+2], kv);
            kv = k4.w * vi; yp = fmaf(r4.w, S[4*g4+3], yp); S[4*g4+3] = fmaf(w4.w, S[4*g4+3], kv);
        }
        if (q) part[q - 1][i] = yp;
        __syncthreads();

        if (q == 0) {
            float yv = yp + part[0][i] + part[1][i] + part[2][i];
            yv = fmaf(ruk[rbase + (size_t)t * H_], vi, yv);
            y[base + (size_t)t * C_ + i] = yv;
        }
        cur = nxt;
    }
}

// ==========================================================================
// GroupNorm * g -> bf16 hi/lo split directly (for the W_o GEMM)
// ==========================================================================
__global__ void k_gnorm(const float* __restrict__ y, const float* __restrict__ gbuf,
                        const float* __restrict__ lnw, const float* __restrict__ lnb,
                        __nv_bfloat16* __restrict__ hi, __nv_bfloat16* __restrict__ lo)
{
    const int row = blockIdx.x;
    const int c   = threadIdx.x;
    size_t idx = (size_t)row * C_ + c;
    float v = y[idx];
    float s = v, s2 = v * v;
#pragma unroll
    for (int off = 16; off; off >>= 1) {
        s  += __shfl_xor_sync(0xffffffffu, s,  off);
        s2 += __shfl_xor_sync(0xffffffffu, s2, off);
    }
    __shared__ float as[24], as2[24];
    if ((c & 31) == 0) { as[c >> 5] = s; as2[c >> 5] = s2; }
    __syncthreads();
    const int g = c >> 6;
    float sum  = as[2 * g]  + as[2 * g + 1];
    float sum2 = as2[2 * g] + as2[2 * g + 1];
    float mu   = sum * (1.f / 64.f);
    float var  = sum2 * (1.f / 64.f) - mu * mu;
    float nv   = (v - mu) * rsqrtf(var + 1e-5f);
    float val  = fmaf(nv, lnw[c], lnb[c]) * gbuf[idx];
    __nv_bfloat16 h = __float2bfloat16(val);
    hi[idx] = h;
    lo[idx] = __float2bfloat16(val - __bfloat162float(h));
}

// ==========================================================================
// Host launcher
// ==========================================================================
extern "C" void kernel_launch(void* const* d_in, const int* in_sizes, int n_in,
                              void* d_out, int out_size)
{
    const float* x     = (const float*)d_in[0];
    const float* W_r   = (const float*)d_in[1];
    const float* W_k   = (const float*)d_in[2];
    const float* W_v   = (const float*)d_in[3];
    const float* W_g   = (const float*)d_in[4];
    const float* W_o   = (const float*)d_in[5];
    const float* maa_x = (const float*)d_in[6];
    const float* maa_w = (const float*)d_in[7];
    const float* maa_k = (const float*)d_in[8];
    const float* maa_v = (const float*)d_in[9];
    const float* maa_r = (const float*)d_in[10];
    const float* maa_g = (const float*)d_in[11];
    const float* maa_w1= (const float*)d_in[12];
    const float* maa_w2= (const float*)d_in[13];
    const float* tdec  = (const float*)d_in[14];
    const float* dec_w1= (const float*)d_in[15];
    const float* dec_w2= (const float*)d_in[16];
    const float* faaaa = (const float*)d_in[17];
    const float* ln_w  = (const float*)d_in[18];
    const float* ln_b  = (const float*)d_in[19];
    (void)in_sizes; (void)n_in; (void)out_size;

    float* S = nullptr;
    cudaGetSymbolAddress((void**)&S, g_scratch);
    __nv_bfloat16 *acthi = nullptr, *actlo = nullptr, *w5hi = nullptr, *w5lo = nullptr;
    cudaGetSymbolAddress((void**)&acthi, g_acthi);
    cudaGetSymbolAddress((void**)&actlo, g_actlo);
    cudaGetSymbolAddress((void**)&w5hi, g_w5hi);
    cudaGetSymbolAddress((void**)&w5lo, g_w5lo);

    float* xx   = S + OFF_XX;
    float* xxx  = S + OFF_XXX;
    float* t5   = S + OFF_T5;
    float* xw   = S + OFF_XW;
    float* rb   = S + OFF_R;
    float* kb   = S + OFF_K;
    float* vb   = S + OFF_V;
    float* gb   = S + OFF_G;
    float* h1   = S + OFF_H1;
    float* wdec = S + OFF_WDEC;
    float* yb   = S + OFF_Y;
    float* ruk  = S + OFF_RUK;
    float* outp = (float*)d_out;

    const dim3 gTC(C_ / 128, NR_ / 128);   // (6, 64)

    // 0. split all 5 weights
    k_split5<<<(unsigned)(5 * WSZ_ / 4 / 256), 256>>>(W_r, W_k, W_v, W_g, W_o, w5hi, w5lo);

    // 1. shift + xxx (float4)
    k_shift<<<(unsigned)(NC_ / 4 / 256), 256>>>(x, maa_x, xx, xxx);

    // 2. t5 = tanh(xxx @ maa_w1)
    k_gemm<1, false><<<dim3(2, NR_ / 128), 256>>>(xxx, maa_w1, t5, NR_, 160, C_, nullptr);

    // 3. fused token mix -> xw fp32 + bf16 hi/lo for k,v,r,g
    k_mix<<<dim3(NR_ / 64, C_ / 128), 256>>>(x, xx, t5, maa_w2,
                                             maa_w, maa_k, maa_v, maa_r, maa_g,
                                             xw, acthi, actlo);

    // 4. big NT GEMMs (bf16-split mma.sync). act slots: 0=k,1=v,2=r,3=g
    k_gemm_mma<<<gTC, 256>>>(acthi + 2 * NC_, actlo + 2 * NC_,
                             w5hi + 0 * WSZ_, w5lo + 0 * WSZ_, rb, 0);
    k_gemm_mma<<<gTC, 256>>>(acthi + 0 * NC_, actlo + 0 * NC_,
                             w5hi + 1 * WSZ_, w5lo + 1 * WSZ_, kb, 0);
    k_gemm_mma<<<gTC, 256>>>(acthi + 1 * NC_, actlo + 1 * NC_,
                             w5hi + 2 * WSZ_, w5lo + 2 * WSZ_, vb, 0);
    k_gemm_mma<<<gTC, 256>>>(acthi + 3 * NC_, actlo + 3 * NC_,
                             w5hi + 3 * WSZ_, w5lo + 3 * WSZ_, gb, 1);  // relu

    // 5. decay path (small fp32 GEMMs)
    k_gemm<1, false><<<dim3(1, NR_ / 128), 256>>>(xw, dec_w1, h1, NR_, 64, C_, nullptr);
    k_gemm<3, false><<<dim3(C_ / 128, NR_ / 128), 256>>>(h1, dec_w2, wdec, NR_, C_, 64, tdec);

    // 6. wkv recurrence
    k_ruk<<<NR_, C_>>>(rb, kb, faaaa, ruk);
    k_wkv<<<B_ * H_, 256>>>(rb, kb, vb, wdec, ruk, yb);

    // 7. groupnorm * g -> bf16 pair (reuse act slot 0)
    k_gnorm<<<NR_, C_>>>(yb, gb, ln_w, ln_b, acthi, actlo);

    // 8. out = yn @ W_o^T
    k_gemm_mma<<<gTC, 256>>>(acthi, actlo,
                             w5hi + 4 * WSZ_, w5lo + 4 * WSZ_, outp, 0);
}

// round 11
// speedup vs baseline: 1.1096x; 1.0515x over previous
#include <cuda_runtime.h>
#include <cuda_bf16.h>
#include <math.h>
#include <stdint.h>

// ---------------- problem constants (fixed shapes) ----------------
#define B_   8
#define T_   1024
#define C_   768
#define H_   12
#define HS_  64
#define PH_  32
#define PW_  32
#define NR_  (B_ * T_)          // 8192 rows
#define NC_  ((size_t)NR_ * C_) // 6291456 elems
#define WSZ_ ((size_t)C_ * C_)  // 589824

// ---------------- scratch ----------------
__device__ __align__(16) float g_scratch[10 * NC_ + (size_t)NR_ * 160 + (size_t)NR_ * 64 + (size_t)NR_ * H_];
__device__ __align__(16) __nv_bfloat16 g_acthi[4 * NC_];   // slots: 0=k,1=v,2=r,3=g
__device__ __align__(16) __nv_bfloat16 g_actlo[4 * NC_];
__device__ __align__(16) __nv_bfloat16 g_w5hi[5 * WSZ_];   // W_r,W_k,W_v,W_g,W_o
__device__ __align__(16) __nv_bfloat16 g_w5lo[5 * WSZ_];

#define OFF_XX   ((size_t)0)
#define OFF_XXX  (OFF_XX  + NC_)
#define OFF_T5   (OFF_XXX + NC_)
#define OFF_XW   (OFF_T5  + (size_t)NR_ * 160)
#define OFF_R    (OFF_XW  + NC_)      // R,K,V,G contiguous (4*NC_) for batched GEMM
#define OFF_K    (OFF_R   + NC_)
#define OFF_V    (OFF_K   + NC_)
#define OFF_G    (OFF_V   + NC_)
#define OFF_H1   (OFF_G   + NC_)
#define OFF_WDEC (OFF_H1  + (size_t)NR_ * 64)
#define OFF_Y    (OFF_WDEC+ NC_)
#define OFF_RUK  (OFF_Y   + NC_)

// ========================= helpers ==========================
__device__ __forceinline__ uint32_t smem_u32(const void* p) {
    uint32_t a;
    asm("{ .reg .u64 t; cvta.to.shared.u64 t, %1; cvt.u32.u64 %0, t; }" : "=r"(a) : "l"(p));
    return a;
}
__device__ __forceinline__ void ldsm_x4(uint32_t* r, uint32_t addr) {
    asm volatile("ldmatrix.sync.aligned.m8n8.x4.shared.b16 {%0,%1,%2,%3}, [%4];"
                 : "=r"(r[0]), "=r"(r[1]), "=r"(r[2]), "=r"(r[3]) : "r"(addr));
}
__device__ __forceinline__ void mma_bf16(float* c, const uint32_t* a, uint32_t b0, uint32_t b1) {
    asm volatile("mma.sync.aligned.m16n8k16.row.col.f32.bf16.bf16.f32 "
                 "{%0,%1,%2,%3}, {%4,%5,%6,%7}, {%8,%9}, {%0,%1,%2,%3};"
                 : "+f"(c[0]), "+f"(c[1]), "+f"(c[2]), "+f"(c[3])
                 : "r"(a[0]), "r"(a[1]), "r"(a[2]), "r"(a[3]), "r"(b0), "r"(b1));
}

// ==========================================================================
// bf16-split tensor-core GEMM body (device inline, used by both launchers)
// ==========================================================================
#define PLANE_   2080
#define ATILE_   (4 * PLANE_)
#define BUFSZ_   (2 * ATILE_)

__device__ __forceinline__ void gemm_mma_body(
    const __nv_bfloat16* __restrict__ Ahi, const __nv_bfloat16* __restrict__ Alo,
    const __nv_bfloat16* __restrict__ Whi, const __nv_bfloat16* __restrict__ Wlo,
    float* __restrict__ Cmat, int doRelu, char* sm)
{
    const int tid  = threadIdx.x;
    const int warp = tid >> 5;
    const int lane = tid & 31;
    const int m0 = blockIdx.y * 128;
    const int n0 = blockIdx.x * 128;
    const int wm = warp >> 2;
    const int wn = warp & 3;

    float acc[4][4][4];
#pragma unroll
    for (int i = 0; i < 4; i++)
#pragma unroll
        for (int j = 0; j < 4; j++)
#pragma unroll
            for (int q = 0; q < 4; q++) acc[i][j][q] = 0.f;

    const int ldrow = tid >> 1;
    const int ldcb  = (tid & 1) * 2;

    uint4 ra[2], rb[2];

    const uint32_t sb = smem_u32(sm);
    const int lgrp = lane >> 3;
    const int lrl  = lane & 7;

#define LDG_T(c_)                                                               \
    {                                                                           \
        const int seg_ = (c_) / 24;                                             \
        const int kc_  = ((c_) % 24) * 32;                                      \
        const __nv_bfloat16* Ag = (seg_ == 1) ? Alo : Ahi;                      \
        const __nv_bfloat16* Bg = (seg_ == 2) ? Wlo : Whi;                      \
        const __nv_bfloat16* ap = Ag + (size_t)(m0 + ldrow) * C_ + kc_ + ldcb * 8; \
        const __nv_bfloat16* bp = Bg + (size_t)(n0 + ldrow) * C_ + kc_ + ldcb * 8; \
        ra[0] = *(const uint4*)ap; ra[1] = *(const uint4*)(ap + 8);             \
        rb[0] = *(const uint4*)bp; rb[1] = *(const uint4*)(bp + 8);             \
    }

#define STS_T(buf_)                                                             \
    {                                                                           \
        char* b_ = sm + (buf_) * BUFSZ_;                                        \
        *(uint4*)(b_ + (ldcb + 0) * PLANE_ + ldrow * 16) = ra[0];               \
        *(uint4*)(b_ + (ldcb + 1) * PLANE_ + ldrow * 16) = ra[1];               \
        *(uint4*)(b_ + ATILE_ + (ldcb + 0) * PLANE_ + ldrow * 16) = rb[0];      \
        *(uint4*)(b_ + ATILE_ + (ldcb + 1) * PLANE_ + ldrow * 16) = rb[1];      \
    }

    LDG_T(0);
    STS_T(0);
    __syncthreads();

    for (int c = 0; c < 72; c++) {
        const int buf = c & 1;
        const bool hasNext = (c + 1 < 72);
        if (hasNext) LDG_T(c + 1);

        const uint32_t abase = sb + buf * BUFSZ_;
        const uint32_t bbase = abase + ATILE_;

#pragma unroll
        for (int kk = 0; kk < 2; kk++) {
            uint32_t afr[4][4], bfr[2][4];
#pragma unroll
            for (int mt = 0; mt < 4; mt++) {
                int row   = wm * 64 + mt * 16 + (lgrp & 1) * 8 + lrl;
                int chunk = kk * 2 + (lgrp >> 1);
                ldsm_x4(afr[mt], abase + chunk * PLANE_ + row * 16);
            }
#pragma unroll
            for (int nt = 0; nt < 2; nt++) {
                int nr    = wn * 32 + nt * 16 + (lgrp >> 1) * 8 + lrl;
                int chunk = kk * 2 + (lgrp & 1);
                ldsm_x4(bfr[nt], bbase + chunk * PLANE_ + nr * 16);
            }
#pragma unroll
            for (int mt = 0; mt < 4; mt++)
#pragma unroll
                for (int ng = 0; ng < 4; ng++)
                    mma_bf16(acc[mt][ng], afr[mt], bfr[ng >> 1][(ng & 1) * 2 + 0],
                             bfr[ng >> 1][(ng & 1) * 2 + 1]);
        }

        if (hasNext) {
            STS_T(buf ^ 1);
            __syncthreads();
        }
    }
#undef LDG_T
#undef STS_T

#pragma unroll
    for (int mt = 0; mt < 4; mt++) {
        const int r0 = m0 + wm * 64 + mt * 16 + (lane >> 2);
#pragma unroll
        for (int ng = 0; ng < 4; ng++) {
            const int col = n0 + wn * 32 + ng * 8 + (lane & 3) * 2;
            float c0 = acc[mt][ng][0], c1 = acc[mt][ng][1];
            float c2 = acc[mt][ng][2], c3 = acc[mt][ng][3];
            if (doRelu) {
                c0 = fmaxf(c0, 0.f); c1 = fmaxf(c1, 0.f);
                c2 = fmaxf(c2, 0.f); c3 = fmaxf(c3, 0.f);
            }
            *(float2*)(Cmat + (size_t)r0 * C_ + col)       = make_float2(c0, c1);
            *(float2*)(Cmat + (size_t)(r0 + 8) * C_ + col) = make_float2(c2, c3);
        }
    }
}

// Batched r/k/v/g GEMMs: gridDim.z = 4 selects act slot / weight / output.
__global__ void __launch_bounds__(256, 2)
k_gemm_mma4(const __nv_bfloat16* __restrict__ acthi, const __nv_bfloat16* __restrict__ actlo,
            const __nv_bfloat16* __restrict__ w5hi, const __nv_bfloat16* __restrict__ w5lo,
            float* __restrict__ outbase)
{
    __shared__ __align__(16) char sm[2 * BUFSZ_];
    const int z = blockIdx.z;
    // weight order: z=0:W_r,1:W_k,2:W_v,3:W_g ; act slots: r=2,k=0,v=1,g=3
    const int aslot = (z == 0) ? 2 : (z == 1) ? 0 : (z == 2) ? 1 : 3;
    gemm_mma_body(acthi + (size_t)aslot * NC_, actlo + (size_t)aslot * NC_,
                  w5hi + (size_t)z * WSZ_, w5lo + (size_t)z * WSZ_,
                  outbase + (size_t)z * NC_, z == 3, sm);
}

// Single GEMM (W_o path)
__global__ void __launch_bounds__(256, 2)
k_gemm_mma(const __nv_bfloat16* __restrict__ Ahi, const __nv_bfloat16* __restrict__ Alo,
           const __nv_bfloat16* __restrict__ Whi, const __nv_bfloat16* __restrict__ Wlo,
           float* __restrict__ Cmat, int doRelu)
{
    __shared__ __align__(16) char sm[2 * BUFSZ_];
    gemm_mma_body(Ahi, Alo, Whi, Wlo, Cmat, doRelu, sm);
}

// ==========================================================================
// Split all five weight matrices into bf16 hi/lo once (float4 vectorized).
// ==========================================================================
__global__ void __launch_bounds__(256)
k_split5(const float* __restrict__ w0, const float* __restrict__ w1,
         const float* __restrict__ w2, const float* __restrict__ w3,
         const float* __restrict__ w4,
         __nv_bfloat16* __restrict__ hi, __nv_bfloat16* __restrict__ lo)
{
    size_t i4 = (size_t)blockIdx.x * blockDim.x + threadIdx.x;
    size_t idx = i4 * 4;
    int sel = (int)(idx / WSZ_);
    size_t off = idx % WSZ_;
    const float* src = (sel == 0) ? w0 : (sel == 1) ? w1 : (sel == 2) ? w2 : (sel == 3) ? w3 : w4;
    float4 a = *(const float4*)(src + off);
    __nv_bfloat16 h0 = __float2bfloat16(a.x);
    __nv_bfloat16 h1 = __float2bfloat16(a.y);
    __nv_bfloat16 h2 = __float2bfloat16(a.z);
    __nv_bfloat16 h3 = __float2bfloat16(a.w);
    __nv_bfloat162 hp0, hp1, lp0, lp1;
    hp0.x = h0; hp0.y = h1; hp1.x = h2; hp1.y = h3;
    lp0.x = __float2bfloat16(a.x - __bfloat162float(h0));
    lp0.y = __float2bfloat16(a.y - __bfloat162float(h1));
    lp1.x = __float2bfloat16(a.z - __bfloat162float(h2));
    lp1.y = __float2bfloat16(a.w - __bfloat162float(h3));
    *(uint2*)(hi + idx) = make_uint2(*(uint32_t*)&hp0, *(uint32_t*)&hp1);
    *(uint2*)(lo + idx) = make_uint2(*(uint32_t*)&lp0, *(uint32_t*)&lp1);
}

// ==========================================================================
// Kernel 1: q-shift (float4) -> xx = shift(x) - x ; xxx = x + xx * maa_x
// ==========================================================================
__global__ void __launch_bounds__(256)
k_shift(const float* __restrict__ x, const float* __restrict__ maa_x,
        float* __restrict__ xx, float* __restrict__ xxx)
{
    size_t i4 = (size_t)blockIdx.x * blockDim.x + threadIdx.x;
    size_t idx = i4 * 4;
    int c  = (int)(idx % C_);
    int bt = (int)(idx / C_);
    int t  = bt % T_;
    int w  = t % PW_;
    int h  = t / PW_;
    int quarter = (c & (HS_ - 1)) >> 4;

    float4 src = make_float4(0.f, 0.f, 0.f, 0.f);
    if (quarter == 0)      { if (w > 0)       src = *(const float4*)(x + idx - C_); }
    else if (quarter == 1) { if (w < PW_ - 1) src = *(const float4*)(x + idx + C_); }
    else if (quarter == 2) { if (h > 0)       src = *(const float4*)(x + idx - PW_ * C_); }
    else                   { if (h < PH_ - 1) src = *(const float4*)(x + idx + PW_ * C_); }

    float4 xv = *(const float4*)(x + idx);
    float4 mv = *(const float4*)(maa_x + c);
    float4 d, o;
    d.x = src.x - xv.x; d.y = src.y - xv.y; d.z = src.z - xv.z; d.w = src.w - xv.w;
    o.x = fmaf(d.x, mv.x, xv.x); o.y = fmaf(d.y, mv.y, xv.y);
    o.z = fmaf(d.z, mv.z, xv.z); o.w = fmaf(d.w, mv.w, xv.w);
    *(float4*)(xx + idx)  = d;
    *(float4*)(xxx + idx) = o;
}

// ==========================================================================
// Pipelined tiled fp32 GEMM (small N/K GEMMs only)
// ==========================================================================
template<int EPI, bool BNT>
__global__ void __launch_bounds__(256, 2)
k_gemm(const float* __restrict__ A, const float* __restrict__ B,
       float* __restrict__ Cmat, int M, int N, int K, const float* __restrict__ bias)
{
    __shared__ float As[2][16][132];
    __shared__ float Bs[2][16][132];

    const int m0   = blockIdx.y * 128;
    const int n0   = blockIdx.x * 128;
    const int tid  = threadIdx.x;
    const int warp = tid >> 5;
    const int lane = tid & 31;
    const int tm   = (warp >> 2) * 64 + (lane >> 2) * 8;
    const int tn   = (warp & 3) * 32 + (lane & 3) * 8;

    float acc[8][8];
#pragma unroll
    for (int i = 0; i < 8; i++)
#pragma unroll
        for (int j = 0; j < 8; j++) acc[i][j] = 0.f;

    float4 aR[2], bR[2];

#define LDG_TILE(k0_)                                                          \
    {                                                                          \
        _Pragma("unroll")                                                      \
        for (int l = 0; l < 2; l++) {                                          \
            int e  = tid + l * 256;                                            \
            int am = e >> 2;                                                   \
            int ak = (e & 3) * 4;                                              \
            aR[l] = *(const float4*)(A + (size_t)(m0 + am) * K + (k0_) + ak);  \
            if (BNT) {                                                         \
                int bn = e >> 2;                                               \
                int bk = (e & 3) * 4;                                          \
                bR[l] = make_float4(0.f, 0.f, 0.f, 0.f);                       \
                if (n0 + bn < N)                                               \
                    bR[l] = *(const float4*)(B + (size_t)(n0 + bn) * K + (k0_) + bk); \
            } else {                                                           \
                int bk = e >> 5;                                               \
                int bn = (e & 31) * 4;                                         \
                bR[l] = make_float4(0.f, 0.f, 0.f, 0.f);                       \
                if (n0 + bn < N)                                               \
                    bR[l] = *(const float4*)(B + (size_t)((k0_) + bk) * N + n0 + bn); \
            }                                                                  \
        }                                                                      \
    }

#define STS_TILE(buf_)                                                         \
    {                                                                          \
        _Pragma("unroll")                                                      \
        for (int l = 0; l < 2; l++) {                                          \
            int e  = tid + l * 256;                                            \
            int am = e >> 2;                                                   \
            int ak = (e & 3) * 4;                                              \
            As[buf_][ak + 0][am] = aR[l].x; As[buf_][ak + 1][am] = aR[l].y;    \
            As[buf_][ak + 2][am] = aR[l].z; As[buf_][ak + 3][am] = aR[l].w;    \
            if (BNT) {                                                         \
                int bn = e >> 2;                                               \
                int bk = (e & 3) * 4;                                          \
                Bs[buf_][bk + 0][bn] = bR[l].x; Bs[buf_][bk + 1][bn] = bR[l].y;\
                Bs[buf_][bk + 2][bn] = bR[l].z; Bs[buf_][bk + 3][bn] = bR[l].w;\
            } else {                                                           \
                int bk = e >> 5;                                               \
                int bn = (e & 31) * 4;                                         \
                *(float4*)(&Bs[buf_][bk][bn]) = bR[l];                         \
            }                                                                  \
        }                                                                      \
    }

    LDG_TILE(0);
    STS_TILE(0);
    __syncthreads();

    int buf = 0;
    for (int k0 = 0; k0 < K; k0 += 16) {
        const bool hasNext = (k0 + 16 < K);
        if (hasNext) LDG_TILE(k0 + 16);

#pragma unroll
        for (int kk = 0; kk < 16; kk++) {
            float a[8], b[8];
            *(float4*)(a)     = *(const float4*)(&As[buf][kk][tm]);
            *(float4*)(a + 4) = *(const float4*)(&As[buf][kk][tm + 4]);
            *(float4*)(b)     = *(const float4*)(&Bs[buf][kk][tn]);
            *(float4*)(b + 4) = *(const float4*)(&Bs[buf][kk][tn + 4]);
#pragma unroll
            for (int i = 0; i < 8; i++)
#pragma unroll
                for (int j = 0; j < 8; j++)
                    acc[i][j] = fmaf(a[i], b[j], acc[i][j]);
        }

        if (hasNext) {
            STS_TILE(buf ^ 1);
            __syncthreads();
            buf ^= 1;
        }
    }
#undef LDG_TILE
#undef STS_TILE

#pragma unroll
    for (int i = 0; i < 8; i++) {
        int m = m0 + tm + i;
#pragma unroll
        for (int j = 0; j < 8; j++) {
            int n = n0 + tn + j;
            if (n < N) {
                float v = acc[i][j];
                if (EPI == 1) v = tanhf(v);
                else if (EPI == 2) v = fmaxf(v, 0.f);
                else if (EPI == 3) v = expf(-expf(bias[n] + v));
                Cmat[(size_t)m * N + n] = v;
            }
        }
    }
}

// ==========================================================================
// Fused token-mix v4 (R10 winner, unchanged): 64-row blocks, column pairs.
// ==========================================================================
__global__ void __launch_bounds__(256, 2)
k_mix(const float* __restrict__ x, const float* __restrict__ xx,
      const float* __restrict__ t5, const float* __restrict__ w2,
      const float* __restrict__ ma0, const float* __restrict__ ma1,
      const float* __restrict__ ma2, const float* __restrict__ ma3,
      const float* __restrict__ ma4,
      float* __restrict__ xw,
      __nv_bfloat16* __restrict__ acthi, __nv_bfloat16* __restrict__ actlo)
{
    const int r0  = blockIdx.x * 64;
    const int c0  = blockIdx.y * 128;
    const int tid = threadIdx.x;
    const int cp  = (tid & 63) * 2;
    const int rh  = tid >> 6;

    __shared__ __align__(16) float tsh[64][36];

    float2 mfv[5];
    mfv[0] = *(const float2*)(ma0 + c0 + cp);
    mfv[1] = *(const float2*)(ma1 + c0 + cp);
    mfv[2] = *(const float2*)(ma2 + c0 + cp);
    mfv[3] = *(const float2*)(ma3 + c0 + cp);
    mfv[4] = *(const float2*)(ma4 + c0 + cp);

    for (int f = 0; f < 5; f++) {
#pragma unroll
        for (int l = 0; l < 8; l++) {
            int e = tid + l * 256;
            tsh[e >> 5][e & 31] = t5[(size_t)(r0 + (e >> 5)) * 160 + f * 32 + (e & 31)];
        }
        float2 wreg[32];
#pragma unroll
        for (int rr = 0; rr < 32; rr++)
            wreg[rr] = *(const float2*)(w2 + (size_t)(f * 32 + rr) * C_ + c0 + cp);
        __syncthreads();

        const float2 mf = mfv[f];
        const size_t slotoff = (size_t)(f - 1) * NC_;
        size_t idx = (size_t)(r0 + rh) * C_ + c0 + cp;

#pragma unroll 4
        for (int it = 0; it < 16; it++) {
            const int row = rh + it * 4;
            float2 xv  = *(const float2*)(x + idx);
            float2 xxv = *(const float2*)(xx + idx);
            const float4* trow = (const float4*)(&tsh[row][0]);
            float a0 = 0.f, a1 = 0.f;
#pragma unroll
            for (int q = 0; q < 8; q++) {
                float4 t4 = trow[q];
                float2 w0 = wreg[4 * q + 0], w1 = wreg[4 * q + 1];
                float2 w2r = wreg[4 * q + 2], w3 = wreg[4 * q + 3];
                a0 = fmaf(t4.x, w0.x, a0); a1 = fmaf(t4.x, w0.y, a1);
                a0 = fmaf(t4.y, w1.x, a0); a1 = fmaf(t4.y, w1.y, a1);
                a0 = fmaf(t4.z, w2r.x, a0); a1 = fmaf(t4.z, w2r.y, a1);
                a0 = fmaf(t4.w, w3.x, a0); a1 = fmaf(t4.w, w3.y, a1);
            }
            float v0 = fmaf(xxv.x, mf.x + a0, xv.x);
            float v1 = fmaf(xxv.y, mf.y + a1, xv.y);
            if (f == 0) {
                *(float2*)(xw + idx) = make_float2(v0, v1);
            } else {
                __nv_bfloat162 hp, lp;
                hp.x = __float2bfloat16(v0);
                hp.y = __float2bfloat16(v1);
                lp.x = __float2bfloat16(v0 - __bfloat162float(hp.x));
                lp.y = __float2bfloat16(v1 - __bfloat162float(hp.y));
                *(uint32_t*)(acthi + slotoff + idx) = *(uint32_t*)&hp;
                *(uint32_t*)(actlo + slotoff + idx) = *(uint32_t*)&lp;
            }
            idx += 4 * C_;
        }
        __syncthreads();
    }
}

// ==========================================================================
// ruk[row,h] = sum_j r*u*k
// ==========================================================================
__global__ void k_ruk(const float* __restrict__ r, const float* __restrict__ k,
                      const float* __restrict__ u, float* __restrict__ ruk)
{
    const int row = blockIdx.x;
    const int c   = threadIdx.x;
    const int h   = c >> 6;
    const int j   = c & 63;
    size_t idx = (size_t)row * C_ + c;
    float p = r[idx] * u[c] * k[idx];
#pragma unroll
    for (int off = 16; off; off >>= 1) p += __shfl_xor_sync(0xffffffffu, p, off);
    __shared__ float ws[24];
    if ((c & 31) == 0) ws[c >> 5] = p;
    __syncthreads();
    if (j == 0) ruk[(size_t)row * H_ + h] = ws[2 * h] + ws[2 * h + 1];
}

// ==========================================================================
// WKV6 recurrence (256 threads, j split in quarters)
// ==========================================================================
__global__ void __launch_bounds__(256)
k_wkv(const float* __restrict__ r, const float* __restrict__ k,
      const float* __restrict__ v, const float* __restrict__ wd,
      const float* __restrict__ ruk, float* __restrict__ y)
{
    const int bh = blockIdx.x;
    const int b  = bh / H_;
    const int h  = bh % H_;
    const int tid = threadIdx.x;
    const int i  = tid & 63;
    const int q  = tid >> 6;

    __shared__ __align__(16) float sr[64];
    __shared__ __align__(16) float sk[64];
    __shared__ __align__(16) float sw[64];
    __shared__ __align__(16) float sv[64];
    __shared__ float part[3][64];

    float S[16];
#pragma unroll
    for (int jj = 0; jj < 16; jj++) S[jj] = 0.f;

    const size_t base  = (size_t)b * T_ * C_ + h * 64;
    const size_t rbase = (size_t)b * T_ * H_ + h;

    const float* mysrc = (q == 0) ? r : (q == 1) ? k : (q == 2) ? wd : v;
    float cur = mysrc[base + i];

    for (int t = 0; t < T_; t++) {
        if (q == 0)      sr[i] = cur;
        else if (q == 1) sk[i] = cur;
        else if (q == 2) sw[i] = cur;
        else             sv[i] = cur;
        __syncthreads();

        float nxt = cur;
        if (t + 1 < T_) nxt = mysrc[base + (size_t)(t + 1) * C_ + i];

        const float vi = sv[i];
        float yp = 0.f;
#pragma unroll
        for (int g4 = 0; g4 < 4; g4++) {
            float4 r4 = *(const float4*)(sr + q * 16 + g4 * 4);
            float4 k4 = *(const float4*)(sk + q * 16 + g4 * 4);
            float4 w4 = *(const float4*)(sw + q * 16 + g4 * 4);
            float kv;
            kv = k4.x * vi; yp = fmaf(r4.x, S[4*g4+0], yp); S[4*g4+0] = fmaf(w4.x, S[4*g4+0], kv);
            kv = k4.y * vi; yp = fmaf(r4.y, S[4*g4+1], yp); S[4*g4+1] = fmaf(w4.y, S[4*g4+1], kv);
            kv = k4.z * vi; yp = fmaf(r4.z, S[4*g4+2], yp); S[4*g4+2] = fmaf(w4.z, S[4*g4+2], kv);
            kv = k4.w * vi; yp = fmaf(r4.w, S[4*g4+3], yp); S[4*g4+3] = fmaf(w4.w, S[4*g4+3], kv);
        }
        if (q) part[q - 1][i] = yp;
        __syncthreads();

        if (q == 0) {
            float yv = yp + part[0][i] + part[1][i] + part[2][i];
            yv = fmaf(ruk[rbase + (size_t)t * H_], vi, yv);
            y[base + (size_t)t * C_ + i] = yv;
        }
        cur = nxt;
    }
}

// ==========================================================================
// GroupNorm * g -> bf16 hi/lo split directly (for the W_o GEMM)
// ==========================================================================
__global__ void k_gnorm(const float* __restrict__ y, const float* __restrict__ gbuf,
                        const float* __restrict__ lnw, const float* __restrict__ lnb,
                        __nv_bfloat16* __restrict__ hi, __nv_bfloat16* __restrict__ lo)
{
    const int row = blockIdx.x;
    const int c   = threadIdx.x;
    size_t idx = (size_t)row * C_ + c;
    float v = y[idx];
    float s = v, s2 = v * v;
#pragma unroll
    for (int off = 16; off; off >>= 1) {
        s  += __shfl_xor_sync(0xffffffffu, s,  off);
        s2 += __shfl_xor_sync(0xffffffffu, s2, off);
    }
    __shared__ float as[24], as2[24];
    if ((c & 31) == 0) { as[c >> 5] = s; as2[c >> 5] = s2; }
    __syncthreads();
    const int g = c >> 6;
    float sum  = as[2 * g]  + as[2 * g + 1];
    float sum2 = as2[2 * g] + as2[2 * g + 1];
    float mu   = sum * (1.f / 64.f);
    float var  = sum2 * (1.f / 64.f) - mu * mu;
    float nv   = (v - mu) * rsqrtf(var + 1e-5f);
    float val  = fmaf(nv, lnw[c], lnb[c]) * gbuf[idx];
    __nv_bfloat16 h = __float2bfloat16(val);
    hi[idx] = h;
    lo[idx] = __float2bfloat16(val - __bfloat162float(h));
}

// ==========================================================================
// Host launcher
// ==========================================================================
extern "C" void kernel_launch(void* const* d_in, const int* in_sizes, int n_in,
                              void* d_out, int out_size)
{
    const float* x     = (const float*)d_in[0];
    const float* W_r   = (const float*)d_in[1];
    const float* W_k   = (const float*)d_in[2];
    const float* W_v   = (const float*)d_in[3];
    const float* W_g   = (const float*)d_in[4];
    const float* W_o   = (const float*)d_in[5];
    const float* maa_x = (const float*)d_in[6];
    const float* maa_w = (const float*)d_in[7];
    const float* maa_k = (const float*)d_in[8];
    const float* maa_v = (const float*)d_in[9];
    const float* maa_r = (const float*)d_in[10];
    const float* maa_g = (const float*)d_in[11];
    const float* maa_w1= (const float*)d_in[12];
    const float* maa_w2= (const float*)d_in[13];
    const float* tdec  = (const float*)d_in[14];
    const float* dec_w1= (const float*)d_in[15];
    const float* dec_w2= (const float*)d_in[16];
    const float* faaaa = (const float*)d_in[17];
    const float* ln_w  = (const float*)d_in[18];
    const float* ln_b  = (const float*)d_in[19];
    (void)in_sizes; (void)n_in; (void)out_size;

    float* S = nullptr;
    cudaGetSymbolAddress((void**)&S, g_scratch);
    __nv_bfloat16 *acthi = nullptr, *actlo = nullptr, *w5hi = nullptr, *w5lo = nullptr;
    cudaGetSymbolAddress((void**)&acthi, g_acthi);
    cudaGetSymbolAddress((void**)&actlo, g_actlo);
    cudaGetSymbolAddress((void**)&w5hi, g_w5hi);
    cudaGetSymbolAddress((void**)&w5lo, g_w5lo);

    float* xx   = S + OFF_XX;
    float* xxx  = S + OFF_XXX;
    float* t5   = S + OFF_T5;
    float* xw   = S + OFF_XW;
    float* rb   = S + OFF_R;
    float* kb   = S + OFF_K;
    float* vb   = S + OFF_V;
    float* h1   = S + OFF_H1;
    float* wdec = S + OFF_WDEC;
    float* yb   = S + OFF_Y;
    float* ruk  = S + OFF_RUK;
    float* outp = (float*)d_out;

    // 0. split all 5 weights
    k_split5<<<(unsigned)(5 * WSZ_ / 4 / 256), 256>>>(W_r, W_k, W_v, W_g, W_o, w5hi, w5lo);

    // 1. shift + xxx (float4)
    k_shift<<<(unsigned)(NC_ / 4 / 256), 256>>>(x, maa_x, xx, xxx);

    // 2. t5 = tanh(xxx @ maa_w1)
    k_gemm<1, false><<<dim3(2, NR_ / 128), 256>>>(xxx, maa_w1, t5, NR_, 160, C_, nullptr);

    // 3. fused token mix -> xw fp32 + bf16 hi/lo for k,v,r,g
    k_mix<<<dim3(NR_ / 64, C_ / 128), 256>>>(x, xx, t5, maa_w2,
                                             maa_w, maa_k, maa_v, maa_r, maa_g,
                                             xw, acthi, actlo);

    // 4. batched r/k/v/g GEMMs in ONE launch (z = 0..3) -> rb,kb,vb,gb
    k_gemm_mma4<<<dim3(C_ / 128, NR_ / 128, 4), 256>>>(acthi, actlo, w5hi, w5lo, rb);

    // 5. decay path (small fp32 GEMMs)
    k_gemm<1, false><<<dim3(1, NR_ / 128), 256>>>(xw, dec_w1, h1, NR_, 64, C_, nullptr);
    k_gemm<3, false><<<dim3(C_ / 128, NR_ / 128), 256>>>(h1, dec_w2, wdec, NR_, C_, 64, tdec);

    // 6. wkv recurrence
    k_ruk<<<NR_, C_>>>(rb, kb, faaaa, ruk);
    k_wkv<<<B_ * H_, 256>>>(rb, kb, vb, wdec, ruk, yb);

    // 7. groupnorm * g -> bf16 pair (reuse act slot 0; gb = rb + 3*NC_)
    k_gnorm<<<NR_, C_>>>(yb, rb + 3 * NC_, ln_w, ln_b, acthi, actlo);

    // 8. out = yn @ W_o^T
    k_gemm_mma<<<dim3(C_ / 128, NR_ / 128), 256>>>(acthi, actlo,
                                                   w5hi + 4 * WSZ_, w5lo + 4 * WSZ_, outp, 0);
}